// round 10
// baseline (speedup 1.0000x reference)
#include <cuda_runtime.h>
#include <cuda_bf16.h>
#include <cstdint>

typedef unsigned long long ull;

#define B_  32
#define S_  128
#define H_  512
#define D_  512
#define V_  32000
#define F_  768
#define G4  2048   // 4*H

// ---------------- scratch (device globals; no allocation allowed) ----------------
__device__ float g_yim[B_ * D_];
__device__ float g_xU[(S_ + 1) * B_ * G4];
__device__ float g_Wcat[1024 * G4];              // [Wh1 ; M01=Wxh0@Uh1]
__device__ float g_b0eff[G4];
__device__ float g_b1eff[G4];
__device__ float g_hcat[B_ * 1024];              // per row: [h1 | h0']
__device__ float g_c0a[B_ * H_];
__device__ float g_c0b[B_ * H_];
__device__ float g_c1s[B_ * H_];
__device__ float g_part0[8 * B_ * G4];
__device__ float g_part1[16 * B_ * G4];

// bf16 hi/lo operand arrays
__device__ __nv_bfloat16 g_Uh_h[512 * 2048], g_Uh_l[512 * 2048];
__device__ __nv_bfloat16 g_Wx1_h[512 * 512], g_Wx1_l[512 * 512];
__device__ __nv_bfloat16 g_Wc_h[512 * 32000], g_Wc_l[512 * 32000];
__device__ __nv_bfloat16 g_Xg_h[4224 * 512], g_Xg_l[4224 * 512];   // padded 33*128 rows
__device__ __nv_bfloat16 g_H1s_h[4096 * 512], g_H1s_l[4096 * 512];
__device__ __nv_bfloat16 g_ys_h[4096 * 512], g_ys_l[4096 * 512];

// ---------------- helpers ----------------
__device__ __forceinline__ ull pack2(float x, float y) {
    ull r; asm("mov.b64 %0, {%1, %2};" : "=l"(r) : "f"(x), "f"(y)); return r;
}
__device__ __forceinline__ void ffma2(ull& d, ull a, ull b) {
    asm("fma.rn.f32x2 %0, %1, %2, %0;" : "+l"(d) : "l"(a), "l"(b));
}
__device__ __forceinline__ float2 unpack2(ull v) {
    float2 r; asm("mov.b64 {%0, %1}, %2;" : "=f"(r.x), "=f"(r.y) : "l"(v)); return r;
}
__device__ __forceinline__ uint32_t smem_u32(const void* p) {
    return (uint32_t)__cvta_generic_to_shared(p);
}

#define CPA16(dst, src) asm volatile( \
    "cp.async.cg.shared.global [%0], [%1], 16;" :: "r"(dst), "l"(src))
#define CPA_COMMIT asm volatile("cp.async.commit_group;")
#define CPA_WAIT2  asm volatile("cp.async.wait_group 2;")

// split one float4 into packed bf16 hi/lo pairs
__device__ __forceinline__ void split4(float4 v, uint2& ph, uint2& pl) {
    float a[4] = {v.x, v.y, v.z, v.w};
    unsigned h[4], l[4];
    #pragma unroll
    for (int q = 0; q < 4; q++) {
        __nv_bfloat16 hh = __float2bfloat16_rn(a[q]);
        h[q] = (unsigned)__bfloat16_as_ushort(hh);
        l[q] = (unsigned)__bfloat16_as_ushort(
                   __float2bfloat16_rn(a[q] - __bfloat162float(hh)));
    }
    ph = make_uint2(h[0] | (h[1] << 16), h[2] | (h[3] << 16));
    pl = make_uint2(l[0] | (l[1] << 16), l[2] | (l[3] << 16));
}

// ---------------- init ----------------
__global__ void init_state_kernel(const float* __restrict__ h0,
                                  const float* __restrict__ c0,
                                  float* __restrict__ hcat,
                                  float* __restrict__ c0a,
                                  float* __restrict__ c1s) {
    int idx = blockIdx.x * 256 + threadIdx.x;   // 32768
    int l = idx >> 14, b = (idx >> 9) & 31, j = idx & 511;
    float h = h0[idx], c = c0[idx];
    if (l == 0) { hcat[b * 1024 + 512 + j] = h; c0a[b * 512 + j] = c; }
    else        { hcat[b * 1024 + j] = h;       c1s[b * 512 + j] = c; }
}

// ---------------- gather + split fused: Xg hi/lo written directly ----------------
__global__ void gather_kernel(const float* __restrict__ yim,
                              const float* __restrict__ embed,
                              const int* __restrict__ tokens,
                              __nv_bfloat16* __restrict__ Xh,
                              __nv_bfloat16* __restrict__ Xl) {
    int v = blockIdx.x * 256 + threadIdx.x;     // float4 units
    int d4 = v & 127;
    int bt = v >> 7;
    int b = bt & 31;
    int t = bt >> 5;
    const float4* src;
    if (t == 0) src = (const float4*)(yim + b * 512);
    else        src = (const float4*)(embed + (size_t)tokens[b * 128 + (t - 1)] * 512);
    float4 x = src[d4];
    uint2 ph, pl;
    split4(x, ph, pl);
    size_t o = (size_t)bt * 512 + d4 * 4;
    *(uint2*)(Xh + o) = ph;
    *(uint2*)(Xl + o) = pl;
}

// ---------------- bias folds ----------------
__global__ void b1eff_kernel(const float* __restrict__ bw, const float* __restrict__ bu,
                             const float* __restrict__ bxh, const float* __restrict__ Uh,
                             float* __restrict__ b1, float* __restrict__ b0) {
    int n = blockIdx.x * 256 + threadIdx.x;     // 2048
    b0[n] = bw[n] + bu[n];
    float acc = bw[2048 + n] + bu[2048 + n];
    const float* U1 = Uh + 512 * 2048;
    for (int k = 0; k < 512; k++) acc += bxh[k] * U1[k * 2048 + n];
    b1[n] = acc;
}

// ---------------- fp32 -> bf16 hi/lo split (weights) ----------------
__global__ void split_kernel(const float* __restrict__ in,
                             __nv_bfloat16* __restrict__ hi,
                             __nv_bfloat16* __restrict__ lo, int n8) {
    int i = blockIdx.x * 256 + threadIdx.x;
    if (i >= n8) return;
    float4 a = ((const float4*)in)[2 * i];
    float4 b = ((const float4*)in)[2 * i + 1];
    uint2 ph0, pl0, ph1, pl1;
    split4(a, ph0, pl0);
    split4(b, ph1, pl1);
    ((uint4*)hi)[i] = make_uint4(ph0.x, ph0.y, ph1.x, ph1.y);
    ((uint4*)lo)[i] = make_uint4(pl0.x, pl0.y, pl1.x, pl1.y);
}

// ---------------- fp32 SGEMM (small setup matrices) ----------------
__global__ __launch_bounds__(256, 2) void sgemm_kernel(const float* __restrict__ A,
                                                       const float* __restrict__ Bm,
                                                       const float* __restrict__ bias,
                                                       float* __restrict__ C,
                                                       int M, int N, int K) {
    __shared__ __align__(16) float As[16][132];
    __shared__ __align__(16) float Bs[16][128];
    int tid = threadIdx.x;
    int m0 = blockIdx.y * 128, n0 = blockIdx.x * 128;
    int a_m = tid >> 2, a_k = (tid & 3) << 2;
    int b_k = tid >> 5, b_n = (tid & 31) << 2;
    int tm0 = (tid >> 4) << 3, tn0 = (tid & 15) << 3;
    ull acc[8][4];
    #pragma unroll
    for (int i = 0; i < 8; i++)
        #pragma unroll
        for (int j = 0; j < 4; j++) acc[i][j] = 0ULL;

    for (int k0 = 0; k0 < K; k0 += 16) {
        #pragma unroll
        for (int h = 0; h < 2; h++) {
            int gm = m0 + a_m + h * 64;
            float4 av = make_float4(0.f, 0.f, 0.f, 0.f);
            if (gm < M) av = *(const float4*)(A + (size_t)gm * K + k0 + a_k);
            As[a_k + 0][a_m + h * 64] = av.x;
            As[a_k + 1][a_m + h * 64] = av.y;
            As[a_k + 2][a_m + h * 64] = av.z;
            As[a_k + 3][a_m + h * 64] = av.w;
        }
        #pragma unroll
        for (int h = 0; h < 2; h++) {
            int gk = k0 + b_k + h * 8;
            *(float4*)&Bs[b_k + h * 8][b_n] = *(const float4*)(Bm + (size_t)gk * N + n0 + b_n);
        }
        __syncthreads();
        #pragma unroll
        for (int kk = 0; kk < 16; kk++) {
            float4 a0 = *(const float4*)&As[kk][tm0];
            float4 a1 = *(const float4*)&As[kk][tm0 + 4];
            ull b2[4];
            #pragma unroll
            for (int j = 0; j < 4; j++) b2[j] = *(const ull*)&Bs[kk][tn0 + 2 * j];
            float av[8] = {a0.x, a0.y, a0.z, a0.w, a1.x, a1.y, a1.z, a1.w};
            #pragma unroll
            for (int i = 0; i < 8; i++) {
                ull a2 = pack2(av[i], av[i]);
                #pragma unroll
                for (int j = 0; j < 4; j++) ffma2(acc[i][j], a2, b2[j]);
            }
        }
        __syncthreads();
    }
    #pragma unroll
    for (int i = 0; i < 8; i++) {
        int r = m0 + tm0 + i;
        if (r < M) {
            float o_[8];
            #pragma unroll
            for (int j = 0; j < 4; j++) {
                float2 v = unpack2(acc[i][j]);
                o_[2 * j] = v.x; o_[2 * j + 1] = v.y;
            }
            if (bias) {
                #pragma unroll
                for (int j = 0; j < 8; j++) o_[j] += bias[n0 + tn0 + j];
            }
            float* cp = C + (size_t)r * N + n0 + tn0;
            *(float4*)cp = make_float4(o_[0], o_[1], o_[2], o_[3]);
            *(float4*)(cp + 4) = make_float4(o_[4], o_[5], o_[6], o_[7]);
        }
    }
}

// ---------------- bf16-pair tensor-core GEMM, 3-stage cp.async pipeline ----------------
// C = Ah@Bh + Ah@Bl + Al@Bh (+bias). A row-count padded to 128 multiples.
// grid = (M/128 fast, N/128). If Ch != null, writes bf16 hi/lo split output instead of C.
#define LDSM4(r, addr) asm volatile( \
    "ldmatrix.sync.aligned.m8n8.x4.shared.b16 {%0,%1,%2,%3}, [%4];" \
    : "=r"((r)[0]), "=r"((r)[1]), "=r"((r)[2]), "=r"((r)[3]) : "r"(addr))
#define LDSM4T(r, addr) asm volatile( \
    "ldmatrix.sync.aligned.m8n8.x4.trans.shared.b16 {%0,%1,%2,%3}, [%4];" \
    : "=r"((r)[0]), "=r"((r)[1]), "=r"((r)[2]), "=r"((r)[3]) : "r"(addr))
#define MMA16816(d, a, b) asm volatile( \
    "mma.sync.aligned.m16n8k16.row.col.f32.bf16.bf16.f32 " \
    "{%0,%1,%2,%3}, {%4,%5,%6,%7}, {%8,%9}, {%0,%1,%2,%3};" \
    : "+f"((d)[0]), "+f"((d)[1]), "+f"((d)[2]), "+f"((d)[3]) \
    : "r"((a)[0]), "r"((a)[1]), "r"((a)[2]), "r"((a)[3]), "r"((b)[0]), "r"((b)[1]))

// smem layout (dynamic): Ah[3 stages][128][24], Al[3][128][24], Bh[3][16][136], Bl[3][16][136]
#define BFP_A_ST 6144                   // 128*24*2 bytes per stage
#define BFP_B_ST 4352                   // 16*136*2
#define BFP_OAL 18432
#define BFP_OBH 36864
#define BFP_OBL 49920
#define BFP_SMEM 62976

__global__ __launch_bounds__(256, 2) void bfp_gemm_kernel(
    const __nv_bfloat16* __restrict__ Ah, const __nv_bfloat16* __restrict__ Al,
    const __nv_bfloat16* __restrict__ Bh, const __nv_bfloat16* __restrict__ Bl,
    const float* __restrict__ bias, float* __restrict__ C,
    __nv_bfloat16* __restrict__ Ch, __nv_bfloat16* __restrict__ Cl,
    int M, int N, int K, int permute) {
    extern __shared__ __align__(16) char smdyn[];
    uint32_t sb = smem_u32(smdyn);
    int tid = threadIdx.x;
    int lane = tid & 31, wid = tid >> 5;
    int wm = wid >> 2, wn = wid & 3;             // 2 x 4 warps, warp tile 64m x 32n
    int m0 = blockIdx.x * 128, n0 = blockIdx.y * 128;

    uint32_t aAh[4], aAl[4], aBh[2], aBl[2];
    {
        int r = lane & 15, c2 = (lane >> 4) * 8;
        #pragma unroll
        for (int i = 0; i < 4; i++) {
            int row = wm * 64 + i * 16 + r;
            aAh[i] = sb + row * 48 + c2 * 2;
            aAl[i] = sb + BFP_OAL + row * 48 + c2 * 2;
        }
        #pragma unroll
        for (int j2 = 0; j2 < 2; j2++) {
            int col = wn * 32 + j2 * 16 + c2;
            aBh[j2] = sb + BFP_OBH + r * 272 + col * 2;
            aBl[j2] = sb + BFP_OBL + r * 272 + col * 2;
        }
    }

    float acc[4][4][4];
    #pragma unroll
    for (int i = 0; i < 4; i++)
        #pragma unroll
        for (int j = 0; j < 4; j++)
            #pragma unroll
            for (int q = 0; q < 4; q++) acc[i][j][q] = 0.f;

    int arow = tid >> 1, ac0 = (tid & 1) * 8;    // A tile 128x16, 16B/thread/array
    int brow = tid >> 4, bc0 = (tid & 15) * 8;   // B tile 16x128
    const __nv_bfloat16* gAh = Ah + (size_t)(m0 + arow) * K + ac0;
    const __nv_bfloat16* gAl = Al + (size_t)(m0 + arow) * K + ac0;
    const __nv_bfloat16* gBh = Bh + (size_t)brow * N + n0 + bc0;
    const __nv_bfloat16* gBl = Bl + (size_t)brow * N + n0 + bc0;
    uint32_t dAh = sb + arow * 48 + ac0 * 2;
    uint32_t dAl = sb + BFP_OAL + arow * 48 + ac0 * 2;
    uint32_t dBh = sb + BFP_OBH + brow * 272 + bc0 * 2;
    uint32_t dBl = sb + BFP_OBL + brow * 272 + bc0 * 2;

#define BFP_FILL(st, kc) do { \
        CPA16(dAh + (st) * BFP_A_ST, gAh + (kc) * 16); \
        CPA16(dAl + (st) * BFP_A_ST, gAl + (kc) * 16); \
        CPA16(dBh + (st) * BFP_B_ST, gBh + (size_t)(kc) * 16 * N); \
        CPA16(dBl + (st) * BFP_B_ST, gBl + (size_t)(kc) * 16 * N); \
        CPA_COMMIT; \
    } while (0)

    int nk = K / 16;
    BFP_FILL(0, 0);
    BFP_FILL(1, 1);

    int s = 0, fs = 2;
    for (int k = 0; k < nk; k++) {
        if (k + 2 < nk) { BFP_FILL(fs, k + 2); fs = (fs == 2) ? 0 : fs + 1; }
        else            { CPA_COMMIT; }          // keep group count pattern constant
        CPA_WAIT2;                               // oldest (stage s) fill complete
        __syncthreads();
        uint32_t sA = s * BFP_A_ST, sB2 = s * BFP_B_ST;
        uint32_t af[4][4], bh[4][2], bl[4][2];
        #pragma unroll
        for (int i = 0; i < 4; i++) LDSM4(af[i], aAh[i] + sA);
        #pragma unroll
        for (int j2 = 0; j2 < 2; j2++) {
            uint32_t t4[4];
            LDSM4T(t4, aBh[j2] + sB2);
            bh[2 * j2][0] = t4[0]; bh[2 * j2][1] = t4[1];
            bh[2 * j2 + 1][0] = t4[2]; bh[2 * j2 + 1][1] = t4[3];
        }
        #pragma unroll
        for (int i = 0; i < 4; i++)
            #pragma unroll
            for (int j = 0; j < 4; j++) MMA16816(acc[i][j], af[i], bh[j]);   // hi*hi
        #pragma unroll
        for (int j2 = 0; j2 < 2; j2++) {
            uint32_t t4[4];
            LDSM4T(t4, aBl[j2] + sB2);
            bl[2 * j2][0] = t4[0]; bl[2 * j2][1] = t4[1];
            bl[2 * j2 + 1][0] = t4[2]; bl[2 * j2 + 1][1] = t4[3];
        }
        #pragma unroll
        for (int i = 0; i < 4; i++)
            #pragma unroll
            for (int j = 0; j < 4; j++) MMA16816(acc[i][j], af[i], bl[j]);   // hi*lo
        #pragma unroll
        for (int i = 0; i < 4; i++) LDSM4(af[i], aAl[i] + sA);
        #pragma unroll
        for (int i = 0; i < 4; i++)
            #pragma unroll
            for (int j = 0; j < 4; j++) MMA16816(acc[i][j], af[i], bh[j]);   // lo*hi
        __syncthreads();                         // stage (s) free for refill
        s = (s == 2) ? 0 : s + 1;
    }

    // ---- epilogue: fp32 (optional row permute) or bf16 hi/lo split output ----
    #pragma unroll
    for (int i = 0; i < 4; i++) {
        int r0 = m0 + wm * 64 + i * 16 + (lane >> 2);
        #pragma unroll
        for (int h = 0; h < 2; h++) {
            int r = r0 + h * 8;
            if (r < M) {
                #pragma unroll
                for (int j = 0; j < 4; j++) {
                    int c = n0 + wn * 32 + j * 8 + (lane & 3) * 2;
                    float x0 = acc[i][j][h * 2], x1 = acc[i][j][h * 2 + 1];
                    if (bias) { x0 += bias[c]; x1 += bias[c + 1]; }
                    if (Ch) {
                        __nv_bfloat16 h0b = __float2bfloat16_rn(x0);
                        __nv_bfloat16 h1b = __float2bfloat16_rn(x1);
                        __nv_bfloat16 l0b = __float2bfloat16_rn(x0 - __bfloat162float(h0b));
                        __nv_bfloat16 l1b = __float2bfloat16_rn(x1 - __bfloat162float(h1b));
                        uint32_t ph = (uint32_t)__bfloat16_as_ushort(h0b)
                                    | ((uint32_t)__bfloat16_as_ushort(h1b) << 16);
                        uint32_t pl = (uint32_t)__bfloat16_as_ushort(l0b)
                                    | ((uint32_t)__bfloat16_as_ushort(l1b) << 16);
                        *(uint32_t*)(Ch + (size_t)r * N + c) = ph;
                        *(uint32_t*)(Cl + (size_t)r * N + c) = pl;
                    } else {
                        int ro = permute ? ((r & 31) * 128 + (r >> 5)) : r;
                        *(float2*)(C + (size_t)ro * N + c) = make_float2(x0, x1);
                    }
                }
            }
        }
    }
}

// ---------------- LSTM cell pieces ----------------
template<int NSL>
__device__ __forceinline__ void gates4(const float* __restrict__ part,
                                       const float* __restrict__ xU_t,
                                       const float* __restrict__ beff,
                                       int b, int j,
                                       float4& gf, float4& gi, float4& go, float4& gc) {
    gf = make_float4(0.f, 0.f, 0.f, 0.f); gi = gf; go = gf; gc = gf;
    const float* p = part + b * 2048 + j;
    #pragma unroll
    for (int s = 0; s < NSL; s++) {
        float4 a = *(const float4*)(p);
        float4 bq = *(const float4*)(p + 512);
        float4 cq = *(const float4*)(p + 1024);
        float4 dq = *(const float4*)(p + 1536);
        gf.x += a.x;  gf.y += a.y;  gf.z += a.z;  gf.w += a.w;
        gi.x += bq.x; gi.y += bq.y; gi.z += bq.z; gi.w += bq.w;
        go.x += cq.x; go.y += cq.y; go.z += cq.z; go.w += cq.w;
        gc.x += dq.x; gc.y += dq.y; gc.z += dq.z; gc.w += dq.w;
        p += 32 * 2048;
    }
    if (xU_t) {
        const float* x = xU_t + b * 2048 + j;
        float4 a = *(const float4*)(x);
        float4 bq = *(const float4*)(x + 512);
        float4 cq = *(const float4*)(x + 1024);
        float4 dq = *(const float4*)(x + 1536);
        gf.x += a.x;  gf.y += a.y;  gf.z += a.z;  gf.w += a.w;
        gi.x += bq.x; gi.y += bq.y; gi.z += bq.z; gi.w += bq.w;
        go.x += cq.x; go.y += cq.y; go.z += cq.z; go.w += cq.w;
        gc.x += dq.x; gc.y += dq.y; gc.z += dq.z; gc.w += dq.w;
    }
    float4 a = *(const float4*)(beff + j);
    float4 bq = *(const float4*)(beff + 512 + j);
    float4 cq = *(const float4*)(beff + 1024 + j);
    float4 dq = *(const float4*)(beff + 1536 + j);
    gf.x += a.x;  gf.y += a.y;  gf.z += a.z;  gf.w += a.w;
    gi.x += bq.x; gi.y += bq.y; gi.z += bq.z; gi.w += bq.w;
    go.x += cq.x; go.y += cq.y; go.z += cq.z; go.w += cq.w;
    gc.x += dq.x; gc.y += dq.y; gc.z += dq.z; gc.w += dq.w;
}

__device__ __forceinline__ float2 lstm_update(float gf, float gi, float go, float gc,
                                              float c_old) {
    float f  = 1.f / (1.f + __expf(-gf));
    float ii = 1.f / (1.f + __expf(-gi));
    float o  = 1.f / (1.f + __expf(-go));
    float cn = f * c_old + ii * tanhf(gc);
    float hn = o * tanhf(cn);
    return make_float2(hn, cn);
}

__device__ __forceinline__ void lstm4(float4 gf, float4 gi, float4 go, float4 gc,
                                      float4 co, float4& hn, float4& cn) {
    float2 r0 = lstm_update(gf.x, gi.x, go.x, gc.x, co.x);
    float2 r1 = lstm_update(gf.y, gi.y, go.y, gc.y, co.y);
    float2 r2 = lstm_update(gf.z, gi.z, go.z, gc.z, co.z);
    float2 r3 = lstm_update(gf.w, gi.w, go.w, gc.w, co.w);
    hn = make_float4(r0.x, r1.x, r2.x, r3.x);
    cn = make_float4(r0.y, r1.y, r2.y, r3.y);
}

__device__ __forceinline__ void gemm64(const float* __restrict__ Wp,
                                       float* __restrict__ pout,
                                       float (*hs)[36]) {
    ull acc[16];
    #pragma unroll
    for (int q = 0; q < 16; q++) acc[q] = 0ULL;
    for (int k0 = 0; k0 < 64; k0 += 8) {
        float wv[8];
        #pragma unroll
        for (int j = 0; j < 8; j++) wv[j] = Wp[(size_t)(k0 + j) * 2048];
        #pragma unroll
        for (int j = 0; j < 8; j++) {
            ull w2 = pack2(wv[j], wv[j]);
            const float* hr = &hs[k0 + j][0];
            #pragma unroll
            for (int p = 0; p < 8; p++) {
                ulonglong2 hh = *(const ulonglong2*)(hr + p * 4);
                ffma2(acc[2 * p], w2, hh.x);
                ffma2(acc[2 * p + 1], w2, hh.y);
            }
        }
    }
    #pragma unroll
    for (int q = 0; q < 16; q++) {
        float2 v = unpack2(acc[q]);
        pout[(2 * q) * 2048] = v.x;
        pout[(2 * q + 1) * 2048] = v.y;
    }
}

// bootstrap layer-0 GEMM (t=0): grid (16,8), 128 thr
__global__ __launch_bounds__(128) void cell_gemm_kernel(const float* __restrict__ A,
                                                        const float* __restrict__ W,
                                                        float* __restrict__ part) {
    __shared__ __align__(16) float hs[64][36];
    int tid = threadIdx.x;
    int kbase = blockIdx.y * 64;
    for (int i = tid; i < 2048; i += 128) {
        int b = i >> 6, kk = i & 63;
        hs[kk][b] = A[b * 1024 + kbase + kk];
    }
    __syncthreads();
    int ncol = blockIdx.x * 128 + tid;
    gemm64(W + (size_t)kbase * 2048 + ncol,
           part + (size_t)(blockIdx.y * 32) * 2048 + ncol, hs);
}

// step A: fused combine0 + layer-1 GEMM.  grid (8 nb, 16 ks), 256 threads.
__global__ __launch_bounds__(256) void stepA_kernel(
    const float* __restrict__ Wcat, const float* __restrict__ part0,
    float* __restrict__ part1, const float* __restrict__ xU_t,
    const float* __restrict__ b0eff,
    const float* __restrict__ c0_old, float* __restrict__ c0_new,
    float* __restrict__ hcat) {
    __shared__ __align__(16) float hs[64][36];
    int tid = threadIdx.x, nb = blockIdx.x, ks = blockIdx.y;

    if (ks < 8) {
        if (tid < 64) {
            int idx = (((ks * 8 + nb) * 64) + tid) * 4;
            int b = idx >> 9, j = idx & 511;
            float4 gf, gi, go, gc, hn, cn;
            gates4<8>(part0, xU_t, b0eff, b, j, gf, gi, go, gc);
            lstm4(gf, gi, go, gc, *(const float4*)(c0_old + idx), hn, cn);
            *(float4*)(c0_new + idx) = cn;
            *(float4*)(hcat + b * 1024 + 512 + j) = hn;
        }
        for (int c = tid; c < 512; c += 256) {
            int bb = c >> 4, k4 = (c & 15) * 4;
            float4 v = *(const float4*)(hcat + bb * 1024 + ks * 64 + k4);
            hs[k4 + 0][bb] = v.x; hs[k4 + 1][bb] = v.y;
            hs[k4 + 2][bb] = v.z; hs[k4 + 3][bb] = v.w;
        }
    } else {
        int kslo = ks - 8;
        int bb = tid & 31, jc = tid >> 5;
        #pragma unroll
        for (int h = 0; h < 2; h++) {
            int j = kslo * 64 + jc * 8 + h * 4;
            float4 gf, gi, go, gc, hn, cn;
            gates4<8>(part0, xU_t, b0eff, bb, j, gf, gi, go, gc);
            lstm4(gf, gi, go, gc, *(const float4*)(c0_old + bb * 512 + j), hn, cn);
            int kk = j - kslo * 64;
            hs[kk + 0][bb] = hn.x; hs[kk + 1][bb] = hn.y;
            hs[kk + 2][bb] = hn.z; hs[kk + 3][bb] = hn.w;
        }
    }
    __syncthreads();
    int ncol = nb * 256 + tid;
    gemm64(Wcat + (size_t)(ks * 64) * 2048 + ncol,
           part1 + (size_t)(ks * 32) * 2048 + ncol, hs);
}

// step B: fused combine1 + next step's layer-0 GEMM.  grid (8 nb, 8 ks), 256 threads.
__global__ __launch_bounds__(256) void stepB_kernel(
    const float* __restrict__ Wh, const float* __restrict__ part1,
    float* __restrict__ part0, const float* __restrict__ b1eff,
    float* __restrict__ c1s, float* __restrict__ hcat,
    __nv_bfloat16* __restrict__ H1h_t, __nv_bfloat16* __restrict__ H1l_t) {
    __shared__ __align__(16) float hs[64][36];
    int tid = threadIdx.x, nb = blockIdx.x, ks = blockIdx.y;
    {
        int g = (ks * 8 + nb) * 256 + tid;
        if (g < 4096) {
            int idx = g * 4;
            int b = idx >> 9, j = idx & 511;
            float4 gf, gi, go, gc, hn, cn;
            gates4<16>(part1, nullptr, b1eff, b, j, gf, gi, go, gc);
            lstm4(gf, gi, go, gc, *(const float4*)(c1s + idx), hn, cn);
            *(float4*)(c1s + idx) = cn;
            *(float4*)(hcat + b * 1024 + j) = hn;
            if (H1h_t) {
                uint2 ph, pl;
                split4(hn, ph, pl);
                *(uint2*)(H1h_t + idx) = ph;
                *(uint2*)(H1l_t + idx) = pl;
            }
        }
    }
    for (int c = tid; c < 512; c += 256) {
        int bb = c >> 4, k4 = (c & 15) * 4;
        float4 v = *(const float4*)(hcat + bb * 1024 + 512 + ks * 64 + k4);
        hs[k4 + 0][bb] = v.x; hs[k4 + 1][bb] = v.y;
        hs[k4 + 2][bb] = v.z; hs[k4 + 3][bb] = v.w;
    }
    __syncthreads();
    int ncol = nb * 256 + tid;
    gemm64(Wh + (size_t)(ks * 64) * 2048 + ncol,
           part0 + (size_t)(ks * 32) * 2048 + ncol, hs);
}

// final standalone combine (t = S)
__global__ void cell_combine_kernel(const float* __restrict__ part,
                                    const float* __restrict__ b1eff,
                                    float* __restrict__ c1s,
                                    __nv_bfloat16* __restrict__ h1h,
                                    __nv_bfloat16* __restrict__ h1l) {
    int idx = (blockIdx.x * 256 + threadIdx.x) * 4;
    int b = idx >> 9, j = idx & 511;
    float4 gf, gi, go, gc, hn, cn;
    gates4<16>(part, nullptr, b1eff, b, j, gf, gi, go, gc);
    lstm4(gf, gi, go, gc, *(const float4*)(c1s + idx), hn, cn);
    *(float4*)(c1s + idx) = cn;
    uint2 ph, pl;
    split4(hn, ph, pl);
    *(uint2*)(h1h + idx) = ph;
    *(uint2*)(h1l + idx) = pl;
}

// ---------------- host orchestration ----------------
extern "C" void kernel_launch(void* const* d_in, const int* in_sizes, int n_in,
                              void* d_out, int out_size) {
    const float* im_feat = (const float*)d_in[0];
    const int*   tokens  = (const int*)d_in[1];
    const float* h0      = (const float*)d_in[2];
    const float* c0      = (const float*)d_in[3];
    const float* embed   = (const float*)d_in[4];
    const float* W_im    = (const float*)d_in[5];
    const float* b_im    = (const float*)d_in[6];
    const float* Wh      = (const float*)d_in[7];
    const float* bw      = (const float*)d_in[8];
    const float* Uh      = (const float*)d_in[9];
    const float* bu      = (const float*)d_in[10];
    const float* Wxh     = (const float*)d_in[11];
    const float* bxh     = (const float*)d_in[12];
    const float* Wc      = (const float*)d_in[13];
    const float* bc      = (const float*)d_in[14];
    float* out = (float*)d_out;

    float *yim, *xU, *Wcat, *b0eff, *b1eff, *hcat, *c0a, *c0b, *c1s, *part0, *part1;
    __nv_bfloat16 *Uh_h, *Uh_l, *Wx1_h, *Wx1_l, *Wc_h, *Wc_l, *Xg_h, *Xg_l,
                  *H1_h, *H1_l, *ys_h, *ys_l;
    cudaGetSymbolAddress((void**)&yim,   g_yim);
    cudaGetSymbolAddress((void**)&xU,    g_xU);
    cudaGetSymbolAddress((void**)&Wcat,  g_Wcat);
    cudaGetSymbolAddress((void**)&b0eff, g_b0eff);
    cudaGetSymbolAddress((void**)&b1eff, g_b1eff);
    cudaGetSymbolAddress((void**)&hcat,  g_hcat);
    cudaGetSymbolAddress((void**)&c0a,   g_c0a);
    cudaGetSymbolAddress((void**)&c0b,   g_c0b);
    cudaGetSymbolAddress((void**)&c1s,   g_c1s);
    cudaGetSymbolAddress((void**)&part0, g_part0);
    cudaGetSymbolAddress((void**)&part1, g_part1);
    cudaGetSymbolAddress((void**)&Uh_h,  g_Uh_h);
    cudaGetSymbolAddress((void**)&Uh_l,  g_Uh_l);
    cudaGetSymbolAddress((void**)&Wx1_h, g_Wx1_h);
    cudaGetSymbolAddress((void**)&Wx1_l, g_Wx1_l);
    cudaGetSymbolAddress((void**)&Wc_h,  g_Wc_h);
    cudaGetSymbolAddress((void**)&Wc_l,  g_Wc_l);
    cudaGetSymbolAddress((void**)&Xg_h,  g_Xg_h);
    cudaGetSymbolAddress((void**)&Xg_l,  g_Xg_l);
    cudaGetSymbolAddress((void**)&H1_h,  g_H1s_h);
    cudaGetSymbolAddress((void**)&H1_l,  g_H1s_l);
    cudaGetSymbolAddress((void**)&ys_h,  g_ys_h);
    cudaGetSymbolAddress((void**)&ys_l,  g_ys_l);

    cudaFuncSetAttribute(bfp_gemm_kernel,
                         cudaFuncAttributeMaxDynamicSharedMemorySize, BFP_SMEM);

    // ---- setup ----
    init_state_kernel<<<128, 256>>>(h0, c0, hcat, c0a, c1s);
    sgemm_kernel<<<dim3(D_ / 128, 1), 256>>>(im_feat, W_im, b_im, yim, B_, D_, F_);
    gather_kernel<<<((S_ + 1) * B_ * D_ / 4) / 256, 256>>>(yim, embed, tokens,
                                                           Xg_h, Xg_l);

    // weight splits (independent)
    split_kernel<<<(512 * 2048 / 8 + 255) / 256, 256>>>(Uh, Uh_h, Uh_l, 512 * 2048 / 8);
    split_kernel<<<(512 * 512 / 8 + 255) / 256, 256>>>(Wxh + (size_t)H_ * D_,
                                                       Wx1_h, Wx1_l, 512 * 512 / 8);
    split_kernel<<<(512 * 32000 / 8 + 255) / 256, 256>>>(Wc, Wc_h, Wc_l, 512 * 32000 / 8);

    // xU = Xg @ Uh0   [4128,512]@[512,2048]
    bfp_gemm_kernel<<<dim3(33, G4 / 128), 256, BFP_SMEM>>>(
        Xg_h, Xg_l, Uh_h, Uh_l, nullptr, xU, nullptr, nullptr,
        (S_ + 1) * B_, G4, D_, 0);
    // Wcat = [Wh1 ; Wxh0 @ Uh1]  (fp32 — recurrence weights stay full precision)
    cudaMemcpyAsync(Wcat, Wh + (size_t)H_ * G4, sizeof(float) * H_ * G4,
                    cudaMemcpyDeviceToDevice, 0);
    sgemm_kernel<<<dim3(G4 / 128, H_ / 128), 256>>>(
        Wxh, Uh + (size_t)D_ * G4, nullptr, Wcat + (size_t)H_ * G4, H_, G4, H_);
    b1eff_kernel<<<G4 / 256, 256>>>(bw, bu, bxh, Uh, b1eff, b0eff);

    // ---- recurrence: bootstrap + 2 kernels per step ----
    cell_gemm_kernel<<<dim3(16, 8), 128>>>(hcat + 512, Wh, part0);
    for (int t = 0; t <= S_; t++) {
        const float* c0r = (t & 1) ? c0b : c0a;
        float* c0w       = (t & 1) ? c0a : c0b;
        stepA_kernel<<<dim3(8, 16), 256>>>(Wcat, part0, part1, xU + (size_t)t * B_ * G4,
                                           b0eff, c0r, c0w, hcat);
        if (t < S_) {
            __nv_bfloat16* hh = (t > 0) ? (H1_h + (size_t)(t - 1) * B_ * H_) : nullptr;
            __nv_bfloat16* hl = (t > 0) ? (H1_l + (size_t)(t - 1) * B_ * H_) : nullptr;
            stepB_kernel<<<dim3(8, 8), 256>>>(Wh, part1, part0, b1eff, c1s, hcat, hh, hl);
        } else {
            cell_combine_kernel<<<16, 256>>>(part1, b1eff, c1s,
                                             H1_h + (size_t)(S_ - 1) * B_ * H_,
                                             H1_l + (size_t)(S_ - 1) * B_ * H_);
        }
    }

    // ---- output path ----
    // ys = H1s @ Wxh1 + bxh1  [4096,512]@[512,512], bf16-pair output fused
    bfp_gemm_kernel<<<dim3(S_ * B_ / 128, D_ / 128), 256, BFP_SMEM>>>(
        H1_h, H1_l, Wx1_h, Wx1_l, bxh + D_, nullptr, ys_h, ys_l,
        S_ * B_, D_, H_, 0);
    // logits = ys @ Wc + bc   [4096,512]@[512,32000], rows (t,b)->(b,t)
    bfp_gemm_kernel<<<dim3(S_ * B_ / 128, V_ / 128), 256, BFP_SMEM>>>(
        ys_h, ys_l, Wc_h, Wc_l, bc, out, nullptr, nullptr,
        S_ * B_, V_, D_, 1);
}

// round 11
// speedup vs baseline: 1.5100x; 1.5100x over previous
#include <cuda_runtime.h>
#include <cuda_bf16.h>
#include <cstdint>

typedef unsigned long long ull;

#define B_  32
#define S_  128
#define H_  512
#define D_  512
#define V_  32000
#define F_  768
#define G4  2048   // 4*H

// ---------------- scratch (device globals; no allocation allowed) ----------------
__device__ float g_yim[B_ * D_];
__device__ float g_xU[(S_ + 1) * B_ * G4];
__device__ float g_Wcat[1024 * G4];              // [Wh1 ; M01=Wxh0@Uh1]
__device__ float g_b0eff[G4];
__device__ float g_b1eff[G4];
__device__ float g_hcat[B_ * 1024];              // per row: [h1 | h0']
__device__ float g_c0a[B_ * H_];
__device__ float g_c0b[B_ * H_];
__device__ float g_c1s[B_ * H_];
__device__ float g_part0[8 * B_ * G4];
__device__ float g_part1[16 * B_ * G4];
__device__ float g_ys[S_ * B_ * D_];

// bf16 hi/lo operand arrays
__device__ __nv_bfloat16 g_Uh_h[512 * 2048], g_Uh_l[512 * 2048];
__device__ __nv_bfloat16 g_Wx1_h[512 * 512], g_Wx1_l[512 * 512];
__device__ __nv_bfloat16 g_Wc_h[512 * 32000], g_Wc_l[512 * 32000];
__device__ __nv_bfloat16 g_Xg_h[4224 * 512], g_Xg_l[4224 * 512];   // padded 33*128 rows
__device__ __nv_bfloat16 g_H1s_h[4096 * 512], g_H1s_l[4096 * 512];
__device__ __nv_bfloat16 g_ys_h[4096 * 512], g_ys_l[4096 * 512];

// ---------------- helpers ----------------
__device__ __forceinline__ ull pack2(float x, float y) {
    ull r; asm("mov.b64 %0, {%1, %2};" : "=l"(r) : "f"(x), "f"(y)); return r;
}
__device__ __forceinline__ void ffma2(ull& d, ull a, ull b) {
    asm("fma.rn.f32x2 %0, %1, %2, %0;" : "+l"(d) : "l"(a), "l"(b));
}
__device__ __forceinline__ float2 unpack2(ull v) {
    float2 r; asm("mov.b64 {%0, %1}, %2;" : "=f"(r.x), "=f"(r.y) : "l"(v)); return r;
}
__device__ __forceinline__ uint32_t smem_u32(const void* p) {
    return (uint32_t)__cvta_generic_to_shared(p);
}

#define CPA16(dst, src) asm volatile( \
    "cp.async.cg.shared.global [%0], [%1], 16;" :: "r"(dst), "l"(src))
#define CPA_COMMIT asm volatile("cp.async.commit_group;")
#define CPA_WAIT2  asm volatile("cp.async.wait_group 2;")

// split one float4 into packed bf16 hi/lo pairs
__device__ __forceinline__ void split4(float4 v, uint2& ph, uint2& pl) {
    float a[4] = {v.x, v.y, v.z, v.w};
    unsigned h[4], l[4];
    #pragma unroll
    for (int q = 0; q < 4; q++) {
        __nv_bfloat16 hh = __float2bfloat16_rn(a[q]);
        h[q] = (unsigned)__bfloat16_as_ushort(hh);
        l[q] = (unsigned)__bfloat16_as_ushort(
                   __float2bfloat16_rn(a[q] - __bfloat162float(hh)));
    }
    ph = make_uint2(h[0] | (h[1] << 16), h[2] | (h[3] << 16));
    pl = make_uint2(l[0] | (l[1] << 16), l[2] | (l[3] << 16));
}

// ---------------- init ----------------
__global__ void init_state_kernel(const float* __restrict__ h0,
                                  const float* __restrict__ c0,
                                  float* __restrict__ hcat,
                                  float* __restrict__ c0a,
                                  float* __restrict__ c1s) {
    int idx = blockIdx.x * 256 + threadIdx.x;   // 32768
    int l = idx >> 14, b = (idx >> 9) & 31, j = idx & 511;
    float h = h0[idx], c = c0[idx];
    if (l == 0) { hcat[b * 1024 + 512 + j] = h; c0a[b * 512 + j] = c; }
    else        { hcat[b * 1024 + j] = h;       c1s[b * 512 + j] = c; }
}

// ---------------- gather + split fused: Xg hi/lo written directly ----------------
__global__ void gather_kernel(const float* __restrict__ yim,
                              const float* __restrict__ embed,
                              const int* __restrict__ tokens,
                              __nv_bfloat16* __restrict__ Xh,
                              __nv_bfloat16* __restrict__ Xl) {
    int v = blockIdx.x * 256 + threadIdx.x;     // float4 units
    int d4 = v & 127;
    int bt = v >> 7;
    int b = bt & 31;
    int t = bt >> 5;
    const float4* src;
    if (t == 0) src = (const float4*)(yim + b * 512);
    else        src = (const float4*)(embed + (size_t)tokens[b * 128 + (t - 1)] * 512);
    float4 x = src[d4];
    uint2 ph, pl;
    split4(x, ph, pl);
    size_t o = (size_t)bt * 512 + d4 * 4;
    *(uint2*)(Xh + o) = ph;
    *(uint2*)(Xl + o) = pl;
}

// ---------------- bias folds ----------------
__global__ void b1eff_kernel(const float* __restrict__ bw, const float* __restrict__ bu,
                             const float* __restrict__ bxh, const float* __restrict__ Uh,
                             float* __restrict__ b1, float* __restrict__ b0) {
    int n = blockIdx.x * 256 + threadIdx.x;     // 2048
    b0[n] = bw[n] + bu[n];
    float acc = bw[2048 + n] + bu[2048 + n];
    const float* U1 = Uh + 512 * 2048;
    for (int k = 0; k < 512; k++) acc += bxh[k] * U1[k * 2048 + n];
    b1[n] = acc;
}

// ---------------- fp32 -> bf16 hi/lo split ----------------
__global__ void split_kernel(const float* __restrict__ in,
                             __nv_bfloat16* __restrict__ hi,
                             __nv_bfloat16* __restrict__ lo, int n8) {
    int i = blockIdx.x * 256 + threadIdx.x;
    if (i >= n8) return;
    float4 a = ((const float4*)in)[2 * i];
    float4 b = ((const float4*)in)[2 * i + 1];
    uint2 ph0, pl0, ph1, pl1;
    split4(a, ph0, pl0);
    split4(b, ph1, pl1);
    ((uint4*)hi)[i] = make_uint4(ph0.x, ph0.y, ph1.x, ph1.y);
    ((uint4*)lo)[i] = make_uint4(pl0.x, pl0.y, pl1.x, pl1.y);
}

// ---------------- fp32 SGEMM (small setup matrices) ----------------
__global__ __launch_bounds__(256, 2) void sgemm_kernel(const float* __restrict__ A,
                                                       const float* __restrict__ Bm,
                                                       const float* __restrict__ bias,
                                                       float* __restrict__ C,
                                                       int M, int N, int K) {
    __shared__ __align__(16) float As[16][132];
    __shared__ __align__(16) float Bs[16][128];
    int tid = threadIdx.x;
    int m0 = blockIdx.y * 128, n0 = blockIdx.x * 128;
    int a_m = tid >> 2, a_k = (tid & 3) << 2;
    int b_k = tid >> 5, b_n = (tid & 31) << 2;
    int tm0 = (tid >> 4) << 3, tn0 = (tid & 15) << 3;
    ull acc[8][4];
    #pragma unroll
    for (int i = 0; i < 8; i++)
        #pragma unroll
        for (int j = 0; j < 4; j++) acc[i][j] = 0ULL;

    for (int k0 = 0; k0 < K; k0 += 16) {
        #pragma unroll
        for (int h = 0; h < 2; h++) {
            int gm = m0 + a_m + h * 64;
            float4 av = make_float4(0.f, 0.f, 0.f, 0.f);
            if (gm < M) av = *(const float4*)(A + (size_t)gm * K + k0 + a_k);
            As[a_k + 0][a_m + h * 64] = av.x;
            As[a_k + 1][a_m + h * 64] = av.y;
            As[a_k + 2][a_m + h * 64] = av.z;
            As[a_k + 3][a_m + h * 64] = av.w;
        }
        #pragma unroll
        for (int h = 0; h < 2; h++) {
            int gk = k0 + b_k + h * 8;
            *(float4*)&Bs[b_k + h * 8][b_n] = *(const float4*)(Bm + (size_t)gk * N + n0 + b_n);
        }
        __syncthreads();
        #pragma unroll
        for (int kk = 0; kk < 16; kk++) {
            float4 a0 = *(const float4*)&As[kk][tm0];
            float4 a1 = *(const float4*)&As[kk][tm0 + 4];
            ull b2[4];
            #pragma unroll
            for (int j = 0; j < 4; j++) b2[j] = *(const ull*)&Bs[kk][tn0 + 2 * j];
            float av[8] = {a0.x, a0.y, a0.z, a0.w, a1.x, a1.y, a1.z, a1.w};
            #pragma unroll
            for (int i = 0; i < 8; i++) {
                ull a2 = pack2(av[i], av[i]);
                #pragma unroll
                for (int j = 0; j < 4; j++) ffma2(acc[i][j], a2, b2[j]);
            }
        }
        __syncthreads();
    }
    #pragma unroll
    for (int i = 0; i < 8; i++) {
        int r = m0 + tm0 + i;
        if (r < M) {
            float o_[8];
            #pragma unroll
            for (int j = 0; j < 4; j++) {
                float2 v = unpack2(acc[i][j]);
                o_[2 * j] = v.x; o_[2 * j + 1] = v.y;
            }
            if (bias) {
                #pragma unroll
                for (int j = 0; j < 8; j++) o_[j] += bias[n0 + tn0 + j];
            }
            float* cp = C + (size_t)r * N + n0 + tn0;
            *(float4*)cp = make_float4(o_[0], o_[1], o_[2], o_[3]);
            *(float4*)(cp + 4) = make_float4(o_[4], o_[5], o_[6], o_[7]);
        }
    }
}

// ---------------- bf16-pair tensor-core GEMM, 3-stage cp.async pipeline ----------------
// C = Ah@Bh + Ah@Bl + Al@Bh (+bias). A row-count padded to 128 multiples.
// grid = (M/128 fast, N/128). NO min-blocks clause: regs must not spill.
#define LDSM4(r, addr) asm volatile( \
    "ldmatrix.sync.aligned.m8n8.x4.shared.b16 {%0,%1,%2,%3}, [%4];" \
    : "=r"((r)[0]), "=r"((r)[1]), "=r"((r)[2]), "=r"((r)[3]) : "r"(addr))
#define LDSM4T(r, addr) asm volatile( \
    "ldmatrix.sync.aligned.m8n8.x4.trans.shared.b16 {%0,%1,%2,%3}, [%4];" \
    : "=r"((r)[0]), "=r"((r)[1]), "=r"((r)[2]), "=r"((r)[3]) : "r"(addr))
#define MMA16816(d, a, b) asm volatile( \
    "mma.sync.aligned.m16n8k16.row.col.f32.bf16.bf16.f32 " \
    "{%0,%1,%2,%3}, {%4,%5,%6,%7}, {%8,%9}, {%0,%1,%2,%3};" \
    : "+f"((d)[0]), "+f"((d)[1]), "+f"((d)[2]), "+f"((d)[3]) \
    : "r"((a)[0]), "r"((a)[1]), "r"((a)[2]), "r"((a)[3]), "r"((b)[0]), "r"((b)[1]))

// dyn smem layout: Ah[3][128][24], Al[3][128][24], Bh[3][16][136], Bl[3][16][136]
#define BFP_A_ST 6144                   // 128*24*2 bytes per stage
#define BFP_B_ST 4352                   // 16*136*2
#define BFP_OAL 18432
#define BFP_OBH 36864
#define BFP_OBL 49920
#define BFP_SMEM 62976

__global__ __launch_bounds__(256) void bfp_gemm_kernel(
    const __nv_bfloat16* __restrict__ Ah, const __nv_bfloat16* __restrict__ Al,
    const __nv_bfloat16* __restrict__ Bh, const __nv_bfloat16* __restrict__ Bl,
    const float* __restrict__ bias, float* __restrict__ C,
    int M, int N, int K, int permute) {
    extern __shared__ __align__(16) char smdyn[];
    uint32_t sb = smem_u32(smdyn);
    int tid = threadIdx.x;
    int lane = tid & 31, wid = tid >> 5;
    int wm = wid >> 2, wn = wid & 3;             // 2 x 4 warps, warp tile 64m x 32n
    int m0 = blockIdx.x * 128, n0 = blockIdx.y * 128;

    uint32_t aAh[4], aAl[4], aBh[2], aBl[2];
    {
        int r = lane & 15, c2 = (lane >> 4) * 8;
        #pragma unroll
        for (int i = 0; i < 4; i++) {
            int row = wm * 64 + i * 16 + r;
            aAh[i] = sb + row * 48 + c2 * 2;
            aAl[i] = sb + BFP_OAL + row * 48 + c2 * 2;
        }
        #pragma unroll
        for (int j2 = 0; j2 < 2; j2++) {
            int col = wn * 32 + j2 * 16 + c2;
            aBh[j2] = sb + BFP_OBH + r * 272 + col * 2;
            aBl[j2] = sb + BFP_OBL + r * 272 + col * 2;
        }
    }

    float acc[4][4][4];
    #pragma unroll
    for (int i = 0; i < 4; i++)
        #pragma unroll
        for (int j = 0; j < 4; j++)
            #pragma unroll
            for (int q = 0; q < 4; q++) acc[i][j][q] = 0.f;

    int arow = tid >> 1, ac0 = (tid & 1) * 8;    // A tile 128x16, 16B/thread/array
    int brow = tid >> 4, bc0 = (tid & 15) * 8;   // B tile 16x128
    const __nv_bfloat16* gAh = Ah + (size_t)(m0 + arow) * K + ac0;
    const __nv_bfloat16* gAl = Al + (size_t)(m0 + arow) * K + ac0;
    const __nv_bfloat16* gBh = Bh + (size_t)brow * N + n0 + bc0;
    const __nv_bfloat16* gBl = Bl + (size_t)brow * N + n0 + bc0;
    uint32_t dAh = sb + arow * 48 + ac0 * 2;
    uint32_t dAl = sb + BFP_OAL + arow * 48 + ac0 * 2;
    uint32_t dBh = sb + BFP_OBH + brow * 272 + bc0 * 2;
    uint32_t dBl = sb + BFP_OBL + brow * 272 + bc0 * 2;

#define BFP_FILL(st, kc) do { \
        CPA16(dAh + (st) * BFP_A_ST, gAh + (kc) * 16); \
        CPA16(dAl + (st) * BFP_A_ST, gAl + (kc) * 16); \
        CPA16(dBh + (st) * BFP_B_ST, gBh + (size_t)(kc) * 16 * N); \
        CPA16(dBl + (st) * BFP_B_ST, gBl + (size_t)(kc) * 16 * N); \
        CPA_COMMIT; \
    } while (0)

    int nk = K / 16;
    BFP_FILL(0, 0);
    BFP_FILL(1, 1);

    int s = 0, fs = 2;
    for (int k = 0; k < nk; k++) {
        if (k + 2 < nk) { BFP_FILL(fs, k + 2); fs = (fs == 2) ? 0 : fs + 1; }
        else            { CPA_COMMIT; }          // keep group-count pattern constant
        CPA_WAIT2;                               // oldest (stage s) fill complete
        __syncthreads();
        uint32_t sA = s * BFP_A_ST, sB2 = s * BFP_B_ST;
        uint32_t af[4][4], bh[4][2], bl[4][2];
        #pragma unroll
        for (int i = 0; i < 4; i++) LDSM4(af[i], aAh[i] + sA);
        #pragma unroll
        for (int j2 = 0; j2 < 2; j2++) {
            uint32_t t4[4];
            LDSM4T(t4, aBh[j2] + sB2);
            bh[2 * j2][0] = t4[0]; bh[2 * j2][1] = t4[1];
            bh[2 * j2 + 1][0] = t4[2]; bh[2 * j2 + 1][1] = t4[3];
        }
        #pragma unroll
        for (int i = 0; i < 4; i++)
            #pragma unroll
            for (int j = 0; j < 4; j++) MMA16816(acc[i][j], af[i], bh[j]);   // hi*hi
        #pragma unroll
        for (int j2 = 0; j2 < 2; j2++) {
            uint32_t t4[4];
            LDSM4T(t4, aBl[j2] + sB2);
            bl[2 * j2][0] = t4[0]; bl[2 * j2][1] = t4[1];
            bl[2 * j2 + 1][0] = t4[2]; bl[2 * j2 + 1][1] = t4[3];
        }
        #pragma unroll
        for (int i = 0; i < 4; i++)
            #pragma unroll
            for (int j = 0; j < 4; j++) MMA16816(acc[i][j], af[i], bl[j]);   // hi*lo
        #pragma unroll
        for (int i = 0; i < 4; i++) LDSM4(af[i], aAl[i] + sA);
        #pragma unroll
        for (int i = 0; i < 4; i++)
            #pragma unroll
            for (int j = 0; j < 4; j++) MMA16816(acc[i][j], af[i], bh[j]);   // lo*hi
        __syncthreads();                         // stage s free for refill
        s = (s == 2) ? 0 : s + 1;
    }

    // ---- epilogue: fp32, optional (t,b)->(b,t) row permute ----
    #pragma unroll
    for (int i = 0; i < 4; i++) {
        int r0 = m0 + wm * 64 + i * 16 + (lane >> 2);
        #pragma unroll
        for (int h = 0; h < 2; h++) {
            int r = r0 + h * 8;
            if (r < M) {
                int ro = permute ? ((r & 31) * 128 + (r >> 5)) : r;
                #pragma unroll
                for (int j = 0; j < 4; j++) {
                    int c = n0 + wn * 32 + j * 8 + (lane & 3) * 2;
                    float x0 = acc[i][j][h * 2], x1 = acc[i][j][h * 2 + 1];
                    if (bias) { x0 += bias[c]; x1 += bias[c + 1]; }
                    *(float2*)(C + (size_t)ro * N + c) = make_float2(x0, x1);
                }
            }
        }
    }
}

// ---------------- LSTM cell pieces ----------------
template<int NSL>
__device__ __forceinline__ void gates4(const float* __restrict__ part,
                                       const float* __restrict__ xU_t,
                                       const float* __restrict__ beff,
                                       int b, int j,
                                       float4& gf, float4& gi, float4& go, float4& gc) {
    gf = make_float4(0.f, 0.f, 0.f, 0.f); gi = gf; go = gf; gc = gf;
    const float* p = part + b * 2048 + j;
    #pragma unroll
    for (int s = 0; s < NSL; s++) {
        float4 a = *(const float4*)(p);
        float4 bq = *(const float4*)(p + 512);
        float4 cq = *(const float4*)(p + 1024);
        float4 dq = *(const float4*)(p + 1536);
        gf.x += a.x;  gf.y += a.y;  gf.z += a.z;  gf.w += a.w;
        gi.x += bq.x; gi.y += bq.y; gi.z += bq.z; gi.w += bq.w;
        go.x += cq.x; go.y += cq.y; go.z += cq.z; go.w += cq.w;
        gc.x += dq.x; gc.y += dq.y; gc.z += dq.z; gc.w += dq.w;
        p += 32 * 2048;
    }
    if (xU_t) {
        const float* x = xU_t + b * 2048 + j;
        float4 a = *(const float4*)(x);
        float4 bq = *(const float4*)(x + 512);
        float4 cq = *(const float4*)(x + 1024);
        float4 dq = *(const float4*)(x + 1536);
        gf.x += a.x;  gf.y += a.y;  gf.z += a.z;  gf.w += a.w;
        gi.x += bq.x; gi.y += bq.y; gi.z += bq.z; gi.w += bq.w;
        go.x += cq.x; go.y += cq.y; go.z += cq.z; go.w += cq.w;
        gc.x += dq.x; gc.y += dq.y; gc.z += dq.z; gc.w += dq.w;
    }
    float4 a = *(const float4*)(beff + j);
    float4 bq = *(const float4*)(beff + 512 + j);
    float4 cq = *(const float4*)(beff + 1024 + j);
    float4 dq = *(const float4*)(beff + 1536 + j);
    gf.x += a.x;  gf.y += a.y;  gf.z += a.z;  gf.w += a.w;
    gi.x += bq.x; gi.y += bq.y; gi.z += bq.z; gi.w += bq.w;
    go.x += cq.x; go.y += cq.y; go.z += cq.z; go.w += cq.w;
    gc.x += dq.x; gc.y += dq.y; gc.z += dq.z; gc.w += dq.w;
}

__device__ __forceinline__ float2 lstm_update(float gf, float gi, float go, float gc,
                                              float c_old) {
    float f  = 1.f / (1.f + __expf(-gf));
    float ii = 1.f / (1.f + __expf(-gi));
    float o  = 1.f / (1.f + __expf(-go));
    float cn = f * c_old + ii * tanhf(gc);
    float hn = o * tanhf(cn);
    return make_float2(hn, cn);
}

__device__ __forceinline__ void lstm4(float4 gf, float4 gi, float4 go, float4 gc,
                                      float4 co, float4& hn, float4& cn) {
    float2 r0 = lstm_update(gf.x, gi.x, go.x, gc.x, co.x);
    float2 r1 = lstm_update(gf.y, gi.y, go.y, gc.y, co.y);
    float2 r2 = lstm_update(gf.z, gi.z, go.z, gc.z, co.z);
    float2 r3 = lstm_update(gf.w, gi.w, go.w, gc.w, co.w);
    hn = make_float4(r0.x, r1.x, r2.x, r3.x);
    cn = make_float4(r0.y, r1.y, r2.y, r3.y);
}

__device__ __forceinline__ void gemm64(const float* __restrict__ Wp,
                                       float* __restrict__ pout,
                                       float (*hs)[36]) {
    ull acc[16];
    #pragma unroll
    for (int q = 0; q < 16; q++) acc[q] = 0ULL;
    for (int k0 = 0; k0 < 64; k0 += 8) {
        float wv[8];
        #pragma unroll
        for (int j = 0; j < 8; j++) wv[j] = Wp[(size_t)(k0 + j) * 2048];
        #pragma unroll
        for (int j = 0; j < 8; j++) {
            ull w2 = pack2(wv[j], wv[j]);
            const float* hr = &hs[k0 + j][0];
            #pragma unroll
            for (int p = 0; p < 8; p++) {
                ulonglong2 hh = *(const ulonglong2*)(hr + p * 4);
                ffma2(acc[2 * p], w2, hh.x);
                ffma2(acc[2 * p + 1], w2, hh.y);
            }
        }
    }
    #pragma unroll
    for (int q = 0; q < 16; q++) {
        float2 v = unpack2(acc[q]);
        pout[(2 * q) * 2048] = v.x;
        pout[(2 * q + 1) * 2048] = v.y;
    }
}

// bootstrap layer-0 GEMM (t=0): grid (16,8), 128 thr
__global__ __launch_bounds__(128) void cell_gemm_kernel(const float* __restrict__ A,
                                                        const float* __restrict__ W,
                                                        float* __restrict__ part) {
    __shared__ __align__(16) float hs[64][36];
    int tid = threadIdx.x;
    int kbase = blockIdx.y * 64;
    for (int i = tid; i < 2048; i += 128) {
        int b = i >> 6, kk = i & 63;
        hs[kk][b] = A[b * 1024 + kbase + kk];
    }
    __syncthreads();
    int ncol = blockIdx.x * 128 + tid;
    gemm64(W + (size_t)kbase * 2048 + ncol,
           part + (size_t)(blockIdx.y * 32) * 2048 + ncol, hs);
}

// step A: fused combine0 + layer-1 GEMM.  grid (8 nb, 16 ks), 256 threads.
__global__ __launch_bounds__(256) void stepA_kernel(
    const float* __restrict__ Wcat, const float* __restrict__ part0,
    float* __restrict__ part1, const float* __restrict__ xU_t,
    const float* __restrict__ b0eff,
    const float* __restrict__ c0_old, float* __restrict__ c0_new,
    float* __restrict__ hcat) {
    __shared__ __align__(16) float hs[64][36];
    int tid = threadIdx.x, nb = blockIdx.x, ks = blockIdx.y;

    if (ks < 8) {
        if (tid < 64) {
            int idx = (((ks * 8 + nb) * 64) + tid) * 4;
            int b = idx >> 9, j = idx & 511;
            float4 gf, gi, go, gc, hn, cn;
            gates4<8>(part0, xU_t, b0eff, b, j, gf, gi, go, gc);
            lstm4(gf, gi, go, gc, *(const float4*)(c0_old + idx), hn, cn);
            *(float4*)(c0_new + idx) = cn;
            *(float4*)(hcat + b * 1024 + 512 + j) = hn;
        }
        for (int c = tid; c < 512; c += 256) {
            int bb = c >> 4, k4 = (c & 15) * 4;
            float4 v = *(const float4*)(hcat + bb * 1024 + ks * 64 + k4);
            hs[k4 + 0][bb] = v.x; hs[k4 + 1][bb] = v.y;
            hs[k4 + 2][bb] = v.z; hs[k4 + 3][bb] = v.w;
        }
    } else {
        int kslo = ks - 8;
        int bb = tid & 31, jc = tid >> 5;
        #pragma unroll
        for (int h = 0; h < 2; h++) {
            int j = kslo * 64 + jc * 8 + h * 4;
            float4 gf, gi, go, gc, hn, cn;
            gates4<8>(part0, xU_t, b0eff, bb, j, gf, gi, go, gc);
            lstm4(gf, gi, go, gc, *(const float4*)(c0_old + bb * 512 + j), hn, cn);
            int kk = j - kslo * 64;
            hs[kk + 0][bb] = hn.x; hs[kk + 1][bb] = hn.y;
            hs[kk + 2][bb] = hn.z; hs[kk + 3][bb] = hn.w;
        }
    }
    __syncthreads();
    int ncol = nb * 256 + tid;
    gemm64(Wcat + (size_t)(ks * 64) * 2048 + ncol,
           part1 + (size_t)(ks * 32) * 2048 + ncol, hs);
}

// step B: fused combine1 + next step's layer-0 GEMM.  grid (8 nb, 8 ks), 256 threads.
__global__ __launch_bounds__(256) void stepB_kernel(
    const float* __restrict__ Wh, const float* __restrict__ part1,
    float* __restrict__ part0, const float* __restrict__ b1eff,
    float* __restrict__ c1s, float* __restrict__ hcat,
    __nv_bfloat16* __restrict__ H1h_t, __nv_bfloat16* __restrict__ H1l_t) {
    __shared__ __align__(16) float hs[64][36];
    int tid = threadIdx.x, nb = blockIdx.x, ks = blockIdx.y;
    {
        int g = (ks * 8 + nb) * 256 + tid;
        if (g < 4096) {
            int idx = g * 4;
            int b = idx >> 9, j = idx & 511;
            float4 gf, gi, go, gc, hn, cn;
            gates4<16>(part1, nullptr, b1eff, b, j, gf, gi, go, gc);
            lstm4(gf, gi, go, gc, *(const float4*)(c1s + idx), hn, cn);
            *(float4*)(c1s + idx) = cn;
            *(float4*)(hcat + b * 1024 + j) = hn;
            if (H1h_t) {
                uint2 ph, pl;
                split4(hn, ph, pl);
                *(uint2*)(H1h_t + idx) = ph;
                *(uint2*)(H1l_t + idx) = pl;
            }
        }
    }
    for (int c = tid; c < 512; c += 256) {
        int bb = c >> 4, k4 = (c & 15) * 4;
        float4 v = *(const float4*)(hcat + bb * 1024 + 512 + ks * 64 + k4);
        hs[k4 + 0][bb] = v.x; hs[k4 + 1][bb] = v.y;
        hs[k4 + 2][bb] = v.z; hs[k4 + 3][bb] = v.w;
    }
    __syncthreads();
    int ncol = nb * 256 + tid;
    gemm64(Wh + (size_t)(ks * 64) * 2048 + ncol,
           part0 + (size_t)(ks * 32) * 2048 + ncol, hs);
}

// final standalone combine (t = S)
__global__ void cell_combine_kernel(const float* __restrict__ part,
                                    const float* __restrict__ b1eff,
                                    float* __restrict__ c1s,
                                    __nv_bfloat16* __restrict__ h1h,
                                    __nv_bfloat16* __restrict__ h1l) {
    int idx = (blockIdx.x * 256 + threadIdx.x) * 4;
    int b = idx >> 9, j = idx & 511;
    float4 gf, gi, go, gc, hn, cn;
    gates4<16>(part, nullptr, b1eff, b, j, gf, gi, go, gc);
    lstm4(gf, gi, go, gc, *(const float4*)(c1s + idx), hn, cn);
    *(float4*)(c1s + idx) = cn;
    uint2 ph, pl;
    split4(hn, ph, pl);
    *(uint2*)(h1h + idx) = ph;
    *(uint2*)(h1l + idx) = pl;
}

// ---------------- host orchestration ----------------
extern "C" void kernel_launch(void* const* d_in, const int* in_sizes, int n_in,
                              void* d_out, int out_size) {
    const float* im_feat = (const float*)d_in[0];
    const int*   tokens  = (const int*)d_in[1];
    const float* h0      = (const float*)d_in[2];
    const float* c0      = (const float*)d_in[3];
    const float* embed   = (const float*)d_in[4];
    const float* W_im    = (const float*)d_in[5];
    const float* b_im    = (const float*)d_in[6];
    const float* Wh      = (const float*)d_in[7];
    const float* bw      = (const float*)d_in[8];
    const float* Uh      = (const float*)d_in[9];
    const float* bu      = (const float*)d_in[10];
    const float* Wxh     = (const float*)d_in[11];
    const float* bxh     = (const float*)d_in[12];
    const float* Wc      = (const float*)d_in[13];
    const float* bc      = (const float*)d_in[14];
    float* out = (float*)d_out;

    float *yim, *xU, *Wcat, *b0eff, *b1eff, *hcat, *c0a, *c0b, *c1s,
          *part0, *part1, *ys;
    __nv_bfloat16 *Uh_h, *Uh_l, *Wx1_h, *Wx1_l, *Wc_h, *Wc_l, *Xg_h, *Xg_l,
                  *H1_h, *H1_l, *ys_h, *ys_l;
    cudaGetSymbolAddress((void**)&yim,   g_yim);
    cudaGetSymbolAddress((void**)&xU,    g_xU);
    cudaGetSymbolAddress((void**)&Wcat,  g_Wcat);
    cudaGetSymbolAddress((void**)&b0eff, g_b0eff);
    cudaGetSymbolAddress((void**)&b1eff, g_b1eff);
    cudaGetSymbolAddress((void**)&hcat,  g_hcat);
    cudaGetSymbolAddress((void**)&c0a,   g_c0a);
    cudaGetSymbolAddress((void**)&c0b,   g_c0b);
    cudaGetSymbolAddress((void**)&c1s,   g_c1s);
    cudaGetSymbolAddress((void**)&part0, g_part0);
    cudaGetSymbolAddress((void**)&part1, g_part1);
    cudaGetSymbolAddress((void**)&ys,    g_ys);
    cudaGetSymbolAddress((void**)&Uh_h,  g_Uh_h);
    cudaGetSymbolAddress((void**)&Uh_l,  g_Uh_l);
    cudaGetSymbolAddress((void**)&Wx1_h, g_Wx1_h);
    cudaGetSymbolAddress((void**)&Wx1_l, g_Wx1_l);
    cudaGetSymbolAddress((void**)&Wc_h,  g_Wc_h);
    cudaGetSymbolAddress((void**)&Wc_l,  g_Wc_l);
    cudaGetSymbolAddress((void**)&Xg_h,  g_Xg_h);
    cudaGetSymbolAddress((void**)&Xg_l,  g_Xg_l);
    cudaGetSymbolAddress((void**)&H1_h,  g_H1s_h);
    cudaGetSymbolAddress((void**)&H1_l,  g_H1s_l);
    cudaGetSymbolAddress((void**)&ys_h,  g_ys_h);
    cudaGetSymbolAddress((void**)&ys_l,  g_ys_l);

    cudaFuncSetAttribute(bfp_gemm_kernel,
                         cudaFuncAttributeMaxDynamicSharedMemorySize, BFP_SMEM);

    // ---- setup ----
    init_state_kernel<<<128, 256>>>(h0, c0, hcat, c0a, c1s);
    sgemm_kernel<<<dim3(D_ / 128, 1), 256>>>(im_feat, W_im, b_im, yim, B_, D_, F_);
    gather_kernel<<<((S_ + 1) * B_ * D_ / 4) / 256, 256>>>(yim, embed, tokens,
                                                           Xg_h, Xg_l);

    // weight splits (independent)
    split_kernel<<<(512 * 2048 / 8 + 255) / 256, 256>>>(Uh, Uh_h, Uh_l, 512 * 2048 / 8);
    split_kernel<<<(512 * 512 / 8 + 255) / 256, 256>>>(Wxh + (size_t)H_ * D_,
                                                       Wx1_h, Wx1_l, 512 * 512 / 8);
    split_kernel<<<(512 * 32000 / 8 + 255) / 256, 256>>>(Wc, Wc_h, Wc_l, 512 * 32000 / 8);

    // xU = Xg @ Uh0   [4128,512]@[512,2048]
    bfp_gemm_kernel<<<dim3(33, G4 / 128), 256, BFP_SMEM>>>(
        Xg_h, Xg_l, Uh_h, Uh_l, nullptr, xU, (S_ + 1) * B_, G4, D_, 0);
    // Wcat = [Wh1 ; Wxh0 @ Uh1]  (fp32 — recurrence weights stay full precision)
    cudaMemcpyAsync(Wcat, Wh + (size_t)H_ * G4, sizeof(float) * H_ * G4,
                    cudaMemcpyDeviceToDevice, 0);
    sgemm_kernel<<<dim3(G4 / 128, H_ / 128), 256>>>(
        Wxh, Uh + (size_t)D_ * G4, nullptr, Wcat + (size_t)H_ * G4, H_, G4, H_);
    b1eff_kernel<<<G4 / 256, 256>>>(bw, bu, bxh, Uh, b1eff, b0eff);

    // ---- recurrence: bootstrap + 2 kernels per step ----
    cell_gemm_kernel<<<dim3(16, 8), 128>>>(hcat + 512, Wh, part0);
    for (int t = 0; t <= S_; t++) {
        const float* c0r = (t & 1) ? c0b : c0a;
        float* c0w       = (t & 1) ? c0a : c0b;
        stepA_kernel<<<dim3(8, 16), 256>>>(Wcat, part0, part1, xU + (size_t)t * B_ * G4,
                                           b0eff, c0r, c0w, hcat);
        if (t < S_) {
            __nv_bfloat16* hh = (t > 0) ? (H1_h + (size_t)(t - 1) * B_ * H_) : nullptr;
            __nv_bfloat16* hl = (t > 0) ? (H1_l + (size_t)(t - 1) * B_ * H_) : nullptr;
            stepB_kernel<<<dim3(8, 8), 256>>>(Wh, part1, part0, b1eff, c1s, hcat, hh, hl);
        } else {
            cell_combine_kernel<<<16, 256>>>(part1, b1eff, c1s,
                                             H1_h + (size_t)(S_ - 1) * B_ * H_,
                                             H1_l + (size_t)(S_ - 1) * B_ * H_);
        }
    }

    // ---- output path ----
    // ys = H1s @ Wxh1 + bxh1  [4096,512]@[512,512] (fp32 out)
    bfp_gemm_kernel<<<dim3(S_ * B_ / 128, D_ / 128), 256, BFP_SMEM>>>(
        H1_h, H1_l, Wx1_h, Wx1_l, bxh + D_, ys, S_ * B_, D_, H_, 0);
    split_kernel<<<(S_ * B_ * D_ / 8 + 255) / 256, 256>>>(ys, ys_h, ys_l,
                                                          S_ * B_ * D_ / 8);
    // logits = ys @ Wc + bc   [4096,512]@[512,32000], rows (t,b)->(b,t)
    bfp_gemm_kernel<<<dim3(S_ * B_ / 128, V_ / 128), 256, BFP_SMEM>>>(
        ys_h, ys_l, Wc_h, Wc_l, bc, out, S_ * B_, V_, D_, 1);
}

// round 14
// speedup vs baseline: 1.6092x; 1.0657x over previous
#include <cuda_runtime.h>
#include <cuda_bf16.h>
#include <cuda_fp16.h>
#include <cstdint>

typedef unsigned long long ull;

#define B_  32
#define S_  128
#define H_  512
#define D_  512
#define V_  32000
#define F_  768
#define G4  2048   // 4*H

// ---------------- scratch (device globals; no allocation allowed) ----------------
__device__ float g_yim[B_ * D_];
__device__ float g_xU[(S_ + 1) * B_ * G4];
__device__ float g_Wcat[1024 * G4];              // [Wh1 ; M01=Wxh0@Uh1]
__device__ float g_b0eff[G4];
__device__ float g_b1eff[G4];
__device__ float g_hcat[B_ * 1024];              // per row: [h1 | h0']
__device__ float g_c0a[B_ * H_];
__device__ float g_c0b[B_ * H_];
__device__ float g_c1s[B_ * H_];
__device__ float g_part0[8 * B_ * G4];
__device__ float g_part1[16 * B_ * G4];
__device__ float g_ys[S_ * B_ * D_];

// bf16 hi/lo operand arrays (3-term path: xU, ys)
__device__ __nv_bfloat16 g_Uh_h[512 * 2048], g_Uh_l[512 * 2048];
__device__ __nv_bfloat16 g_Wx1_h[512 * 512], g_Wx1_l[512 * 512];
__device__ __nv_bfloat16 g_Xg_h[4224 * 512], g_Xg_l[4224 * 512];   // padded 33*128 rows
__device__ __nv_bfloat16 g_H1s_h[4096 * 512], g_H1s_l[4096 * 512];

// fp16 operands (2-term classifier path)
__device__ __half g_Wc16[512 * 32000];           // Wc hi-only fp16
__device__ __half g_ysh_h[4096 * 512], g_ysh_l[4096 * 512];  // ys exact fp16 pair

// ---------------- helpers ----------------
__device__ __forceinline__ ull pack2(float x, float y) {
    ull r; asm("mov.b64 %0, {%1, %2};" : "=l"(r) : "f"(x), "f"(y)); return r;
}
__device__ __forceinline__ void ffma2(ull& d, ull a, ull b) {
    asm("fma.rn.f32x2 %0, %1, %2, %0;" : "+l"(d) : "l"(a), "l"(b));
}
__device__ __forceinline__ float2 unpack2(ull v) {
    float2 r; asm("mov.b64 {%0, %1}, %2;" : "=f"(r.x), "=f"(r.y) : "l"(v)); return r;
}
__device__ __forceinline__ uint32_t smem_u32(const void* p) {
    return (uint32_t)__cvta_generic_to_shared(p);
}

#define CPA16(dst, src) asm volatile( \
    "cp.async.cg.shared.global [%0], [%1], 16;" :: "r"(dst), "l"(src))
#define CPA_COMMIT asm volatile("cp.async.commit_group;")
#define CPA_WAIT2  asm volatile("cp.async.wait_group 2;")

// bf16 split of float4
__device__ __forceinline__ void split4(float4 v, uint2& ph, uint2& pl) {
    float a[4] = {v.x, v.y, v.z, v.w};
    unsigned h[4], l[4];
    #pragma unroll
    for (int q = 0; q < 4; q++) {
        __nv_bfloat16 hh = __float2bfloat16_rn(a[q]);
        h[q] = (unsigned)__bfloat16_as_ushort(hh);
        l[q] = (unsigned)__bfloat16_as_ushort(
                   __float2bfloat16_rn(a[q] - __bfloat162float(hh)));
    }
    ph = make_uint2(h[0] | (h[1] << 16), h[2] | (h[3] << 16));
    pl = make_uint2(l[0] | (l[1] << 16), l[2] | (l[3] << 16));
}

// fp16 split of float4 (exact hi+lo pair)
__device__ __forceinline__ void split4h(float4 v, uint2& ph, uint2& pl) {
    float a[4] = {v.x, v.y, v.z, v.w};
    unsigned h[4], l[4];
    #pragma unroll
    for (int q = 0; q < 4; q++) {
        __half hh = __float2half_rn(a[q]);
        h[q] = (unsigned)__half_as_ushort(hh);
        l[q] = (unsigned)__half_as_ushort(
                   __float2half_rn(a[q] - __half2float(hh)));
    }
    ph = make_uint2(h[0] | (h[1] << 16), h[2] | (h[3] << 16));
    pl = make_uint2(l[0] | (l[1] << 16), l[2] | (l[3] << 16));
}

// ---------------- init ----------------
__global__ void init_state_kernel(const float* __restrict__ h0,
                                  const float* __restrict__ c0,
                                  float* __restrict__ hcat,
                                  float* __restrict__ c0a,
                                  float* __restrict__ c1s) {
    int idx = blockIdx.x * 256 + threadIdx.x;   // 32768
    int l = idx >> 14, b = (idx >> 9) & 31, j = idx & 511;
    float h = h0[idx], c = c0[idx];
    if (l == 0) { hcat[b * 1024 + 512 + j] = h; c0a[b * 512 + j] = c; }
    else        { hcat[b * 1024 + j] = h;       c1s[b * 512 + j] = c; }
}

// ---------------- gather + bf16 split fused ----------------
__global__ void gather_kernel(const float* __restrict__ yim,
                              const float* __restrict__ embed,
                              const int* __restrict__ tokens,
                              __nv_bfloat16* __restrict__ Xh,
                              __nv_bfloat16* __restrict__ Xl) {
    int v = blockIdx.x * 256 + threadIdx.x;     // float4 units
    int d4 = v & 127;
    int bt = v >> 7;
    int b = bt & 31;
    int t = bt >> 5;
    const float4* src;
    if (t == 0) src = (const float4*)(yim + b * 512);
    else        src = (const float4*)(embed + (size_t)tokens[b * 128 + (t - 1)] * 512);
    float4 x = src[d4];
    uint2 ph, pl;
    split4(x, ph, pl);
    size_t o = (size_t)bt * 512 + d4 * 4;
    *(uint2*)(Xh + o) = ph;
    *(uint2*)(Xl + o) = pl;
}

// ---------------- bias folds ----------------
__global__ void b1eff_kernel(const float* __restrict__ bw, const float* __restrict__ bu,
                             const float* __restrict__ bxh, const float* __restrict__ Uh,
                             float* __restrict__ b1, float* __restrict__ b0) {
    int n = blockIdx.x * 256 + threadIdx.x;     // 2048
    b0[n] = bw[n] + bu[n];
    float acc = bw[2048 + n] + bu[2048 + n];
    const float* U1 = Uh + 512 * 2048;
    for (int k = 0; k < 512; k++) acc += bxh[k] * U1[k * 2048 + n];
    b1[n] = acc;
}

// ---------------- fp32 -> bf16 hi/lo split ----------------
__global__ void split_kernel(const float* __restrict__ in,
                             __nv_bfloat16* __restrict__ hi,
                             __nv_bfloat16* __restrict__ lo, int n8) {
    int i = blockIdx.x * 256 + threadIdx.x;
    if (i >= n8) return;
    float4 a = ((const float4*)in)[2 * i];
    float4 b = ((const float4*)in)[2 * i + 1];
    uint2 ph0, pl0, ph1, pl1;
    split4(a, ph0, pl0);
    split4(b, ph1, pl1);
    ((uint4*)hi)[i] = make_uint4(ph0.x, ph0.y, ph1.x, ph1.y);
    ((uint4*)lo)[i] = make_uint4(pl0.x, pl0.y, pl1.x, pl1.y);
}

// ---------------- fp32 -> fp16 hi/lo pair split (for ys) ----------------
__global__ void split_h_kernel(const float* __restrict__ in,
                               __half* __restrict__ hi,
                               __half* __restrict__ lo, int n8) {
    int i = blockIdx.x * 256 + threadIdx.x;
    if (i >= n8) return;
    float4 a = ((const float4*)in)[2 * i];
    float4 b = ((const float4*)in)[2 * i + 1];
    uint2 ph0, pl0, ph1, pl1;
    split4h(a, ph0, pl0);
    split4h(b, ph1, pl1);
    ((uint4*)hi)[i] = make_uint4(ph0.x, ph0.y, ph1.x, ph1.y);
    ((uint4*)lo)[i] = make_uint4(pl0.x, pl0.y, pl1.x, pl1.y);
}

// ---------------- fp32 -> fp16 convert (Wc hi-only) ----------------
__global__ void convert_h_kernel(const float* __restrict__ in,
                                 __half* __restrict__ out, int n8) {
    int i = blockIdx.x * 256 + threadIdx.x;
    if (i >= n8) return;
    float4 a = ((const float4*)in)[2 * i];
    float4 b = ((const float4*)in)[2 * i + 1];
    float v[8] = {a.x, a.y, a.z, a.w, b.x, b.y, b.z, b.w};
    unsigned h[8];
    #pragma unroll
    for (int q = 0; q < 8; q++)
        h[q] = (unsigned)__half_as_ushort(__float2half_rn(v[q]));
    ((uint4*)out)[i] = make_uint4(h[0] | (h[1] << 16), h[2] | (h[3] << 16),
                                  h[4] | (h[5] << 16), h[6] | (h[7] << 16));
}

// ---------------- fp32 SGEMM (small setup matrices) ----------------
__global__ __launch_bounds__(256, 2) void sgemm_kernel(const float* __restrict__ A,
                                                       const float* __restrict__ Bm,
                                                       const float* __restrict__ bias,
                                                       float* __restrict__ C,
                                                       int M, int N, int K) {
    __shared__ __align__(16) float As[16][132];
    __shared__ __align__(16) float Bs[16][128];
    int tid = threadIdx.x;
    int m0 = blockIdx.y * 128, n0 = blockIdx.x * 128;
    int a_m = tid >> 2, a_k = (tid & 3) << 2;
    int b_k = tid >> 5, b_n = (tid & 31) << 2;
    int tm0 = (tid >> 4) << 3, tn0 = (tid & 15) << 3;
    ull acc[8][4];
    #pragma unroll
    for (int i = 0; i < 8; i++)
        #pragma unroll
        for (int j = 0; j < 4; j++) acc[i][j] = 0ULL;

    for (int k0 = 0; k0 < K; k0 += 16) {
        #pragma unroll
        for (int h = 0; h < 2; h++) {
            int gm = m0 + a_m + h * 64;
            float4 av = make_float4(0.f, 0.f, 0.f, 0.f);
            if (gm < M) av = *(const float4*)(A + (size_t)gm * K + k0 + a_k);
            As[a_k + 0][a_m + h * 64] = av.x;
            As[a_k + 1][a_m + h * 64] = av.y;
            As[a_k + 2][a_m + h * 64] = av.z;
            As[a_k + 3][a_m + h * 64] = av.w;
        }
        #pragma unroll
        for (int h = 0; h < 2; h++) {
            int gk = k0 + b_k + h * 8;
            *(float4*)&Bs[b_k + h * 8][b_n] = *(const float4*)(Bm + (size_t)gk * N + n0 + b_n);
        }
        __syncthreads();
        #pragma unroll
        for (int kk = 0; kk < 16; kk++) {
            float4 a0 = *(const float4*)&As[kk][tm0];
            float4 a1 = *(const float4*)&As[kk][tm0 + 4];
            ull b2[4];
            #pragma unroll
            for (int j = 0; j < 4; j++) b2[j] = *(const ull*)&Bs[kk][tn0 + 2 * j];
            float av[8] = {a0.x, a0.y, a0.z, a0.w, a1.x, a1.y, a1.z, a1.w};
            #pragma unroll
            for (int i = 0; i < 8; i++) {
                ull a2 = pack2(av[i], av[i]);
                #pragma unroll
                for (int j = 0; j < 4; j++) ffma2(acc[i][j], a2, b2[j]);
            }
        }
        __syncthreads();
    }
    #pragma unroll
    for (int i = 0; i < 8; i++) {
        int r = m0 + tm0 + i;
        if (r < M) {
            float o_[8];
            #pragma unroll
            for (int j = 0; j < 4; j++) {
                float2 v = unpack2(acc[i][j]);
                o_[2 * j] = v.x; o_[2 * j + 1] = v.y;
            }
            if (bias) {
                #pragma unroll
                for (int j = 0; j < 8; j++) o_[j] += bias[n0 + tn0 + j];
            }
            float* cp = C + (size_t)r * N + n0 + tn0;
            *(float4*)cp = make_float4(o_[0], o_[1], o_[2], o_[3]);
            *(float4*)(cp + 4) = make_float4(o_[4], o_[5], o_[6], o_[7]);
        }
    }
}

// ---------------- shared MMA macros ----------------
#define LDSM4(r, addr) asm volatile( \
    "ldmatrix.sync.aligned.m8n8.x4.shared.b16 {%0,%1,%2,%3}, [%4];" \
    : "=r"((r)[0]), "=r"((r)[1]), "=r"((r)[2]), "=r"((r)[3]) : "r"(addr))
#define LDSM4T(r, addr) asm volatile( \
    "ldmatrix.sync.aligned.m8n8.x4.trans.shared.b16 {%0,%1,%2,%3}, [%4];" \
    : "=r"((r)[0]), "=r"((r)[1]), "=r"((r)[2]), "=r"((r)[3]) : "r"(addr))
#define MMA16816(d, a, b) asm volatile( \
    "mma.sync.aligned.m16n8k16.row.col.f32.bf16.bf16.f32 " \
    "{%0,%1,%2,%3}, {%4,%5,%6,%7}, {%8,%9}, {%0,%1,%2,%3};" \
    : "+f"((d)[0]), "+f"((d)[1]), "+f"((d)[2]), "+f"((d)[3]) \
    : "r"((a)[0]), "r"((a)[1]), "r"((a)[2]), "r"((a)[3]), "r"((b)[0]), "r"((b)[1]))
#define MMAH16816(d, a, b) asm volatile( \
    "mma.sync.aligned.m16n8k16.row.col.f32.f16.f16.f32 " \
    "{%0,%1,%2,%3}, {%4,%5,%6,%7}, {%8,%9}, {%0,%1,%2,%3};" \
    : "+f"((d)[0]), "+f"((d)[1]), "+f"((d)[2]), "+f"((d)[3]) \
    : "r"((a)[0]), "r"((a)[1]), "r"((a)[2]), "r"((a)[3]), "r"((b)[0]), "r"((b)[1]))

// ---------------- bf16 3-term GEMM, 3-stage cp.async pipeline (xU, ys) ----------------
#define BFP_A_ST 6144
#define BFP_B_ST 4352
#define BFP_OAL 18432
#define BFP_OBH 36864
#define BFP_OBL 49920
#define BFP_SMEM 62976

__global__ __launch_bounds__(256) void bfp_gemm_kernel(
    const __nv_bfloat16* __restrict__ Ah, const __nv_bfloat16* __restrict__ Al,
    const __nv_bfloat16* __restrict__ Bh, const __nv_bfloat16* __restrict__ Bl,
    const float* __restrict__ bias, float* __restrict__ C,
    int M, int N, int K, int permute) {
    extern __shared__ __align__(16) char smdyn[];
    uint32_t sb = smem_u32(smdyn);
    int tid = threadIdx.x;
    int lane = tid & 31, wid = tid >> 5;
    int wm = wid >> 2, wn = wid & 3;
    int m0 = blockIdx.x * 128, n0 = blockIdx.y * 128;

    uint32_t aAh[4], aAl[4], aBh[2], aBl[2];
    {
        int r = lane & 15, c2 = (lane >> 4) * 8;
        #pragma unroll
        for (int i = 0; i < 4; i++) {
            int row = wm * 64 + i * 16 + r;
            aAh[i] = sb + row * 48 + c2 * 2;
            aAl[i] = sb + BFP_OAL + row * 48 + c2 * 2;
        }
        #pragma unroll
        for (int j2 = 0; j2 < 2; j2++) {
            int col = wn * 32 + j2 * 16 + c2;
            aBh[j2] = sb + BFP_OBH + r * 272 + col * 2;
            aBl[j2] = sb + BFP_OBL + r * 272 + col * 2;
        }
    }

    float acc[4][4][4];
    #pragma unroll
    for (int i = 0; i < 4; i++)
        #pragma unroll
        for (int j = 0; j < 4; j++)
            #pragma unroll
            for (int q = 0; q < 4; q++) acc[i][j][q] = 0.f;

    int arow = tid >> 1, ac0 = (tid & 1) * 8;
    int brow = tid >> 4, bc0 = (tid & 15) * 8;
    const __nv_bfloat16* gAh = Ah + (size_t)(m0 + arow) * K + ac0;
    const __nv_bfloat16* gAl = Al + (size_t)(m0 + arow) * K + ac0;
    const __nv_bfloat16* gBh = Bh + (size_t)brow * N + n0 + bc0;
    const __nv_bfloat16* gBl = Bl + (size_t)brow * N + n0 + bc0;
    uint32_t dAh = sb + arow * 48 + ac0 * 2;
    uint32_t dAl = sb + BFP_OAL + arow * 48 + ac0 * 2;
    uint32_t dBh = sb + BFP_OBH + brow * 272 + bc0 * 2;
    uint32_t dBl = sb + BFP_OBL + brow * 272 + bc0 * 2;

#define BFP_FILL(st, kc) do { \
        CPA16(dAh + (st) * BFP_A_ST, gAh + (kc) * 16); \
        CPA16(dAl + (st) * BFP_A_ST, gAl + (kc) * 16); \
        CPA16(dBh + (st) * BFP_B_ST, gBh + (size_t)(kc) * 16 * N); \
        CPA16(dBl + (st) * BFP_B_ST, gBl + (size_t)(kc) * 16 * N); \
        CPA_COMMIT; \
    } while (0)

    int nk = K / 16;
    BFP_FILL(0, 0);
    BFP_FILL(1, 1);

    int s = 0, fs = 2;
    for (int k = 0; k < nk; k++) {
        if (k + 2 < nk) { BFP_FILL(fs, k + 2); fs = (fs == 2) ? 0 : fs + 1; }
        else            { CPA_COMMIT; }
        CPA_WAIT2;
        __syncthreads();
        uint32_t sA = s * BFP_A_ST, sB2 = s * BFP_B_ST;
        uint32_t af[4][4], bh[4][2], bl[4][2];
        #pragma unroll
        for (int i = 0; i < 4; i++) LDSM4(af[i], aAh[i] + sA);
        #pragma unroll
        for (int j2 = 0; j2 < 2; j2++) {
            uint32_t t4[4];
            LDSM4T(t4, aBh[j2] + sB2);
            bh[2 * j2][0] = t4[0]; bh[2 * j2][1] = t4[1];
            bh[2 * j2 + 1][0] = t4[2]; bh[2 * j2 + 1][1] = t4[3];
        }
        #pragma unroll
        for (int i = 0; i < 4; i++)
            #pragma unroll
            for (int j = 0; j < 4; j++) MMA16816(acc[i][j], af[i], bh[j]);
        #pragma unroll
        for (int j2 = 0; j2 < 2; j2++) {
            uint32_t t4[4];
            LDSM4T(t4, aBl[j2] + sB2);
            bl[2 * j2][0] = t4[0]; bl[2 * j2][1] = t4[1];
            bl[2 * j2 + 1][0] = t4[2]; bl[2 * j2 + 1][1] = t4[3];
        }
        #pragma unroll
        for (int i = 0; i < 4; i++)
            #pragma unroll
            for (int j = 0; j < 4; j++) MMA16816(acc[i][j], af[i], bl[j]);
        #pragma unroll
        for (int i = 0; i < 4; i++) LDSM4(af[i], aAl[i] + sA);
        #pragma unroll
        for (int i = 0; i < 4; i++)
            #pragma unroll
            for (int j = 0; j < 4; j++) MMA16816(acc[i][j], af[i], bh[j]);
        __syncthreads();
        s = (s == 2) ? 0 : s + 1;
    }

    #pragma unroll
    for (int i = 0; i < 4; i++) {
        int r0 = m0 + wm * 64 + i * 16 + (lane >> 2);
        #pragma unroll
        for (int h = 0; h < 2; h++) {
            int r = r0 + h * 8;
            if (r < M) {
                int ro = permute ? ((r & 31) * 128 + (r >> 5)) : r;
                #pragma unroll
                for (int j = 0; j < 4; j++) {
                    int c = n0 + wn * 32 + j * 8 + (lane & 3) * 2;
                    float x0 = acc[i][j][h * 2], x1 = acc[i][j][h * 2 + 1];
                    if (bias) { x0 += bias[c]; x1 += bias[c + 1]; }
                    *(float2*)(C + (size_t)ro * N + c) = make_float2(x0, x1);
                }
            }
        }
    }
}

// ---------------- fp16 2-term GEMM (classifier): C = (Ah+Al)@Bh + bias ----------------
// dyn smem: Ah[3][128][24], Al[3][128][24], Bh[3][16][136]   (fp16)
#define HFP_A_ST 6144
#define HFP_B_ST 4352
#define HFP_OAL 18432
#define HFP_OBH 36864
#define HFP_SMEM 49920

__global__ __launch_bounds__(256) void hfp_gemm_kernel(
    const __half* __restrict__ Ah, const __half* __restrict__ Al,
    const __half* __restrict__ Bh,
    const float* __restrict__ bias, float* __restrict__ C,
    int M, int N, int K, int permute) {
    extern __shared__ __align__(16) char smdyn[];
    uint32_t sb = smem_u32(smdyn);
    int tid = threadIdx.x;
    int lane = tid & 31, wid = tid >> 5;
    int wm = wid >> 2, wn = wid & 3;             // 2 x 4 warps, warp tile 64m x 32n
    int m0 = blockIdx.x * 128, n0 = blockIdx.y * 128;

    uint32_t aAh[4], aAl[4], aBh[2];
    {
        int r = lane & 15, c2 = (lane >> 4) * 8;
        #pragma unroll
        for (int i = 0; i < 4; i++) {
            int row = wm * 64 + i * 16 + r;
            aAh[i] = sb + row * 48 + c2 * 2;
            aAl[i] = sb + HFP_OAL + row * 48 + c2 * 2;
        }
        #pragma unroll
        for (int j2 = 0; j2 < 2; j2++) {
            int col = wn * 32 + j2 * 16 + c2;
            aBh[j2] = sb + HFP_OBH + r * 272 + col * 2;
        }
    }

    float acc[4][4][4];
    #pragma unroll
    for (int i = 0; i < 4; i++)
        #pragma unroll
        for (int j = 0; j < 4; j++)
            #pragma unroll
            for (int q = 0; q < 4; q++) acc[i][j][q] = 0.f;

    int arow = tid >> 1, ac0 = (tid & 1) * 8;
    int brow = tid >> 4, bc0 = (tid & 15) * 8;
    const __half* gAh = Ah + (size_t)(m0 + arow) * K + ac0;
    const __half* gAl = Al + (size_t)(m0 + arow) * K + ac0;
    const __half* gBh = Bh + (size_t)brow * N + n0 + bc0;
    uint32_t dAh = sb + arow * 48 + ac0 * 2;
    uint32_t dAl = sb + HFP_OAL + arow * 48 + ac0 * 2;
    uint32_t dBh = sb + HFP_OBH + brow * 272 + bc0 * 2;

#define HFP_FILL(st, kc) do { \
        CPA16(dAh + (st) * HFP_A_ST, gAh + (kc) * 16); \
        CPA16(dAl + (st) * HFP_A_ST, gAl + (kc) * 16); \
        CPA16(dBh + (st) * HFP_B_ST, gBh + (size_t)(kc) * 16 * N); \
        CPA_COMMIT; \
    } while (0)

    int nk = K / 16;
    HFP_FILL(0, 0);
    HFP_FILL(1, 1);

    int s = 0, fs = 2;
    for (int k = 0; k < nk; k++) {
        if (k + 2 < nk) { HFP_FILL(fs, k + 2); fs = (fs == 2) ? 0 : fs + 1; }
        else            { CPA_COMMIT; }
        CPA_WAIT2;
        __syncthreads();
        uint32_t sA = s * HFP_A_ST, sB2 = s * HFP_B_ST;
        uint32_t af[4][4], bh[4][2];
        #pragma unroll
        for (int j2 = 0; j2 < 2; j2++) {
            uint32_t t4[4];
            LDSM4T(t4, aBh[j2] + sB2);
            bh[2 * j2][0] = t4[0]; bh[2 * j2][1] = t4[1];
            bh[2 * j2 + 1][0] = t4[2]; bh[2 * j2 + 1][1] = t4[3];
        }
        #pragma unroll
        for (int i = 0; i < 4; i++) LDSM4(af[i], aAh[i] + sA);
        #pragma unroll
        for (int i = 0; i < 4; i++)
            #pragma unroll
            for (int j = 0; j < 4; j++) MMAH16816(acc[i][j], af[i], bh[j]);  // hi@B
        #pragma unroll
        for (int i = 0; i < 4; i++) LDSM4(af[i], aAl[i] + sA);
        #pragma unroll
        for (int i = 0; i < 4; i++)
            #pragma unroll
            for (int j = 0; j < 4; j++) MMAH16816(acc[i][j], af[i], bh[j]);  // lo@B
        __syncthreads();
        s = (s == 2) ? 0 : s + 1;
    }

    #pragma unroll
    for (int i = 0; i < 4; i++) {
        int r0 = m0 + wm * 64 + i * 16 + (lane >> 2);
        #pragma unroll
        for (int h = 0; h < 2; h++) {
            int r = r0 + h * 8;
            if (r < M) {
                int ro = permute ? ((r & 31) * 128 + (r >> 5)) : r;
                #pragma unroll
                for (int j = 0; j < 4; j++) {
                    int c = n0 + wn * 32 + j * 8 + (lane & 3) * 2;
                    float x0 = acc[i][j][h * 2], x1 = acc[i][j][h * 2 + 1];
                    if (bias) { x0 += bias[c]; x1 += bias[c + 1]; }
                    *(float2*)(C + (size_t)ro * N + c) = make_float2(x0, x1);
                }
            }
        }
    }
}

// ---------------- LSTM cell pieces ----------------
template<int NSL>
__device__ __forceinline__ void gates4(const float* __restrict__ part,
                                       const float* __restrict__ xU_t,
                                       const float* __restrict__ beff,
                                       int b, int j,
                                       float4& gf, float4& gi, float4& go, float4& gc) {
    gf = make_float4(0.f, 0.f, 0.f, 0.f); gi = gf; go = gf; gc = gf;
    const float* p = part + b * 2048 + j;
    #pragma unroll
    for (int s = 0; s < NSL; s++) {
        float4 a = *(const float4*)(p);
        float4 bq = *(const float4*)(p + 512);
        float4 cq = *(const float4*)(p + 1024);
        float4 dq = *(const float4*)(p + 1536);
        gf.x += a.x;  gf.y += a.y;  gf.z += a.z;  gf.w += a.w;
        gi.x += bq.x; gi.y += bq.y; gi.z += bq.z; gi.w += bq.w;
        go.x += cq.x; go.y += cq.y; go.z += cq.z; go.w += cq.w;
        gc.x += dq.x; gc.y += dq.y; gc.z += dq.z; gc.w += dq.w;
        p += 32 * 2048;
    }
    if (xU_t) {
        const float* x = xU_t + b * 2048 + j;
        float4 a = *(const float4*)(x);
        float4 bq = *(const float4*)(x + 512);
        float4 cq = *(const float4*)(x + 1024);
        float4 dq = *(const float4*)(x + 1536);
        gf.x += a.x;  gf.y += a.y;  gf.z += a.z;  gf.w += a.w;
        gi.x += bq.x; gi.y += bq.y; gi.z += bq.z; gi.w += bq.w;
        go.x += cq.x; go.y += cq.y; go.z += cq.z; go.w += cq.w;
        gc.x += dq.x; gc.y += dq.y; gc.z += dq.z; gc.w += dq.w;
    }
    float4 a = *(const float4*)(beff + j);
    float4 bq = *(const float4*)(beff + 512 + j);
    float4 cq = *(const float4*)(beff + 1024 + j);
    float4 dq = *(const float4*)(beff + 1536 + j);
    gf.x += a.x;  gf.y += a.y;  gf.z += a.z;  gf.w += a.w;
    gi.x += bq.x; gi.y += bq.y; gi.z += bq.z; gi.w += bq.w;
    go.x += cq.x; go.y += cq.y; go.z += cq.z; go.w += cq.w;
    gc.x += dq.x; gc.y += dq.y; gc.z += dq.z; gc.w += dq.w;
}

__device__ __forceinline__ float2 lstm_update(float gf, float gi, float go, float gc,
                                              float c_old) {
    float f  = 1.f / (1.f + __expf(-gf));
    float ii = 1.f / (1.f + __expf(-gi));
    float o  = 1.f / (1.f + __expf(-go));
    float cn = f * c_old + ii * tanhf(gc);
    float hn = o * tanhf(cn);
    return make_float2(hn, cn);
}

__device__ __forceinline__ void lstm4(float4 gf, float4 gi, float4 go, float4 gc,
                                      float4 co, float4& hn, float4& cn) {
    float2 r0 = lstm_update(gf.x, gi.x, go.x, gc.x, co.x);
    float2 r1 = lstm_update(gf.y, gi.y, go.y, gc.y, co.y);
    float2 r2 = lstm_update(gf.z, gi.z, go.z, gc.z, co.z);
    float2 r3 = lstm_update(gf.w, gi.w, go.w, gc.w, co.w);
    hn = make_float4(r0.x, r1.x, r2.x, r3.x);
    cn = make_float4(r0.y, r1.y, r2.y, r3.y);
}

__device__ __forceinline__ void gemm64(const float* __restrict__ Wp,
                                       float* __restrict__ pout,
                                       float (*hs)[36]) {
    ull acc[16];
    #pragma unroll
    for (int q = 0; q < 16; q++) acc[q] = 0ULL;
    for (int k0 = 0; k0 < 64; k0 += 8) {
        float wv[8];
        #pragma unroll
        for (int j = 0; j < 8; j++) wv[j] = Wp[(size_t)(k0 + j) * 2048];
        #pragma unroll
        for (int j = 0; j < 8; j++) {
            ull w2 = pack2(wv[j], wv[j]);
            const float* hr = &hs[k0 + j][0];
            #pragma unroll
            for (int p = 0; p < 8; p++) {
                ulonglong2 hh = *(const ulonglong2*)(hr + p * 4);
                ffma2(acc[2 * p], w2, hh.x);
                ffma2(acc[2 * p + 1], w2, hh.y);
            }
        }
    }
    #pragma unroll
    for (int q = 0; q < 16; q++) {
        float2 v = unpack2(acc[q]);
        pout[(2 * q) * 2048] = v.x;
        pout[(2 * q + 1) * 2048] = v.y;
    }
}

// bootstrap layer-0 GEMM (t=0): grid (16,8), 128 thr
__global__ __launch_bounds__(128) void cell_gemm_kernel(const float* __restrict__ A,
                                                        const float* __restrict__ W,
                                                        float* __restrict__ part) {
    __shared__ __align__(16) float hs[64][36];
    int tid = threadIdx.x;
    int kbase = blockIdx.y * 64;
    for (int i = tid; i < 2048; i += 128) {
        int b = i >> 6, kk = i & 63;
        hs[kk][b] = A[b * 1024 + kbase + kk];
    }
    __syncthreads();
    int ncol = blockIdx.x * 128 + tid;
    gemm64(W + (size_t)kbase * 2048 + ncol,
           part + (size_t)(blockIdx.y * 32) * 2048 + ncol, hs);
}

// step A: fused combine0 + layer-1 GEMM.  grid (8 nb, 16 ks), 256 threads.
__global__ __launch_bounds__(256) void stepA_kernel(
    const float* __restrict__ Wcat, const float* __restrict__ part0,
    float* __restrict__ part1, const float* __restrict__ xU_t,
    const float* __restrict__ b0eff,
    const float* __restrict__ c0_old, float* __restrict__ c0_new,
    float* __restrict__ hcat) {
    __shared__ __align__(16) float hs[64][36];
    int tid = threadIdx.x, nb = blockIdx.x, ks = blockIdx.y;

    if (ks < 8) {
        if (tid < 64) {
            int idx = (((ks * 8 + nb) * 64) + tid) * 4;
            int b = idx >> 9, j = idx & 511;
            float4 gf, gi, go, gc, hn, cn;
            gates4<8>(part0, xU_t, b0eff, b, j, gf, gi, go, gc);
            lstm4(gf, gi, go, gc, *(const float4*)(c0_old + idx), hn, cn);
            *(float4*)(c0_new + idx) = cn;
            *(float4*)(hcat + b * 1024 + 512 + j) = hn;
        }
        for (int c = tid; c < 512; c += 256) {
            int bb = c >> 4, k4 = (c & 15) * 4;
            float4 v = *(const float4*)(hcat + bb * 1024 + ks * 64 + k4);
            hs[k4 + 0][bb] = v.x; hs[k4 + 1][bb] = v.y;
            hs[k4 + 2][bb] = v.z; hs[k4 + 3][bb] = v.w;
        }
    } else {
        int kslo = ks - 8;
        int bb = tid & 31, jc = tid >> 5;
        #pragma unroll
        for (int h = 0; h < 2; h++) {
            int j = kslo * 64 + jc * 8 + h * 4;
            float4 gf, gi, go, gc, hn, cn;
            gates4<8>(part0, xU_t, b0eff, bb, j, gf, gi, go, gc);
            lstm4(gf, gi, go, gc, *(const float4*)(c0_old + bb * 512 + j), hn, cn);
            int kk = j - kslo * 64;
            hs[kk + 0][bb] = hn.x; hs[kk + 1][bb] = hn.y;
            hs[kk + 2][bb] = hn.z; hs[kk + 3][bb] = hn.w;
        }
    }
    __syncthreads();
    int ncol = nb * 256 + tid;
    gemm64(Wcat + (size_t)(ks * 64) * 2048 + ncol,
           part1 + (size_t)(ks * 32) * 2048 + ncol, hs);
}

// step B: fused combine1 + next step's layer-0 GEMM.  grid (8 nb, 8 ks), 256 threads.
__global__ __launch_bounds__(256) void stepB_kernel(
    const float* __restrict__ Wh, const float* __restrict__ part1,
    float* __restrict__ part0, const float* __restrict__ b1eff,
    float* __restrict__ c1s, float* __restrict__ hcat,
    __nv_bfloat16* __restrict__ H1h_t, __nv_bfloat16* __restrict__ H1l_t) {
    __shared__ __align__(16) float hs[64][36];
    int tid = threadIdx.x, nb = blockIdx.x, ks = blockIdx.y;
    {
        int g = (ks * 8 + nb) * 256 + tid;
        if (g < 4096) {
            int idx = g * 4;
            int b = idx >> 9, j = idx & 511;
            float4 gf, gi, go, gc, hn, cn;
            gates4<16>(part1, nullptr, b1eff, b, j, gf, gi, go, gc);
            lstm4(gf, gi, go, gc, *(const float4*)(c1s + idx), hn, cn);
            *(float4*)(c1s + idx) = cn;
            *(float4*)(hcat + b * 1024 + j) = hn;
            if (H1h_t) {
                uint2 ph, pl;
                split4(hn, ph, pl);
                *(uint2*)(H1h_t + idx) = ph;
                *(uint2*)(H1l_t + idx) = pl;
            }
        }
    }
    for (int c = tid; c < 512; c += 256) {
        int bb = c >> 4, k4 = (c & 15) * 4;
        float4 v = *(const float4*)(hcat + bb * 1024 + 512 + ks * 64 + k4);
        hs[k4 + 0][bb] = v.x; hs[k4 + 1][bb] = v.y;
        hs[k4 + 2][bb] = v.z; hs[k4 + 3][bb] = v.w;
    }
    __syncthreads();
    int ncol = nb * 256 + tid;
    gemm64(Wh + (size_t)(ks * 64) * 2048 + ncol,
           part0 + (size_t)(ks * 32) * 2048 + ncol, hs);
}

// final standalone combine (t = S)
__global__ void cell_combine_kernel(const float* __restrict__ part,
                                    const float* __restrict__ b1eff,
                                    float* __restrict__ c1s,
                                    __nv_bfloat16* __restrict__ h1h,
                                    __nv_bfloat16* __restrict__ h1l) {
    int idx = (blockIdx.x * 256 + threadIdx.x) * 4;
    int b = idx >> 9, j = idx & 511;
    float4 gf, gi, go, gc, hn, cn;
    gates4<16>(part, nullptr, b1eff, b, j, gf, gi, go, gc);
    lstm4(gf, gi, go, gc, *(const float4*)(c1s + idx), hn, cn);
    *(float4*)(c1s + idx) = cn;
    uint2 ph, pl;
    split4(hn, ph, pl);
    *(uint2*)(h1h + idx) = ph;
    *(uint2*)(h1l + idx) = pl;
}

// ---------------- host orchestration ----------------
extern "C" void kernel_launch(void* const* d_in, const int* in_sizes, int n_in,
                              void* d_out, int out_size) {
    const float* im_feat = (const float*)d_in[0];
    const int*   tokens  = (const int*)d_in[1];
    const float* h0      = (const float*)d_in[2];
    const float* c0      = (const float*)d_in[3];
    const float* embed   = (const float*)d_in[4];
    const float* W_im    = (const float*)d_in[5];
    const float* b_im    = (const float*)d_in[6];
    const float* Wh      = (const float*)d_in[7];
    const float* bw      = (const float*)d_in[8];
    const float* Uh      = (const float*)d_in[9];
    const float* bu      = (const float*)d_in[10];
    const float* Wxh     = (const float*)d_in[11];
    const float* bxh     = (const float*)d_in[12];
    const float* Wc      = (const float*)d_in[13];
    const float* bc      = (const float*)d_in[14];
    float* out = (float*)d_out;

    float *yim, *xU, *Wcat, *b0eff, *b1eff, *hcat, *c0a, *c0b, *c1s,
          *part0, *part1, *ys;
    __nv_bfloat16 *Uh_h, *Uh_l, *Wx1_h, *Wx1_l, *Xg_h, *Xg_l, *H1_h, *H1_l;
    __half *Wc16, *ysh_h, *ysh_l;
    cudaGetSymbolAddress((void**)&yim,   g_yim);
    cudaGetSymbolAddress((void**)&xU,    g_xU);
    cudaGetSymbolAddress((void**)&Wcat,  g_Wcat);
    cudaGetSymbolAddress((void**)&b0eff, g_b0eff);
    cudaGetSymbolAddress((void**)&b1eff, g_b1eff);
    cudaGetSymbolAddress((void**)&hcat,  g_hcat);
    cudaGetSymbolAddress((void**)&c0a,   g_c0a);
    cudaGetSymbolAddress((void**)&c0b,   g_c0b);
    cudaGetSymbolAddress((void**)&c1s,   g_c1s);
    cudaGetSymbolAddress((void**)&part0, g_part0);
    cudaGetSymbolAddress((void**)&part1, g_part1);
    cudaGetSymbolAddress((void**)&ys,    g_ys);
    cudaGetSymbolAddress((void**)&Uh_h,  g_Uh_h);
    cudaGetSymbolAddress((void**)&Uh_l,  g_Uh_l);
    cudaGetSymbolAddress((void**)&Wx1_h, g_Wx1_h);
    cudaGetSymbolAddress((void**)&Wx1_l, g_Wx1_l);
    cudaGetSymbolAddress((void**)&Xg_h,  g_Xg_h);
    cudaGetSymbolAddress((void**)&Xg_l,  g_Xg_l);
    cudaGetSymbolAddress((void**)&H1_h,  g_H1s_h);
    cudaGetSymbolAddress((void**)&H1_l,  g_H1s_l);
    cudaGetSymbolAddress((void**)&Wc16,  g_Wc16);
    cudaGetSymbolAddress((void**)&ysh_h, g_ysh_h);
    cudaGetSymbolAddress((void**)&ysh_l, g_ysh_l);

    cudaFuncSetAttribute(bfp_gemm_kernel,
                         cudaFuncAttributeMaxDynamicSharedMemorySize, BFP_SMEM);
    cudaFuncSetAttribute(hfp_gemm_kernel,
                         cudaFuncAttributeMaxDynamicSharedMemorySize, HFP_SMEM);

    // ---- setup ----
    init_state_kernel<<<128, 256>>>(h0, c0, hcat, c0a, c1s);
    sgemm_kernel<<<dim3(D_ / 128, 1), 256>>>(im_feat, W_im, b_im, yim, B_, D_, F_);
    gather_kernel<<<((S_ + 1) * B_ * D_ / 4) / 256, 256>>>(yim, embed, tokens,
                                                           Xg_h, Xg_l);

    // weight splits / converts (independent)
    split_kernel<<<(512 * 2048 / 8 + 255) / 256, 256>>>(Uh, Uh_h, Uh_l, 512 * 2048 / 8);
    split_kernel<<<(512 * 512 / 8 + 255) / 256, 256>>>(Wxh + (size_t)H_ * D_,
                                                       Wx1_h, Wx1_l, 512 * 512 / 8);
    convert_h_kernel<<<(512 * 32000 / 8 + 255) / 256, 256>>>(Wc, Wc16, 512 * 32000 / 8);

    // xU = Xg @ Uh0   [4128,512]@[512,2048]  (bf16 3-term)
    bfp_gemm_kernel<<<dim3(33, G4 / 128), 256, BFP_SMEM>>>(
        Xg_h, Xg_l, Uh_h, Uh_l, nullptr, xU, (S_ + 1) * B_, G4, D_, 0);
    // Wcat = [Wh1 ; Wxh0 @ Uh1]  (fp32)
    cudaMemcpyAsync(Wcat, Wh + (size_t)H_ * G4, sizeof(float) * H_ * G4,
                    cudaMemcpyDeviceToDevice, 0);
    sgemm_kernel<<<dim3(G4 / 128, H_ / 128), 256>>>(
        Wxh, Uh + (size_t)D_ * G4, nullptr, Wcat + (size_t)H_ * G4, H_, G4, H_);
    b1eff_kernel<<<G4 / 256, 256>>>(bw, bu, bxh, Uh, b1eff, b0eff);

    // ---- recurrence: bootstrap + 2 kernels per step ----
    cell_gemm_kernel<<<dim3(16, 8), 128>>>(hcat + 512, Wh, part0);
    for (int t = 0; t <= S_; t++) {
        const float* c0r = (t & 1) ? c0b : c0a;
        float* c0w       = (t & 1) ? c0a : c0b;
        stepA_kernel<<<dim3(8, 16), 256>>>(Wcat, part0, part1, xU + (size_t)t * B_ * G4,
                                           b0eff, c0r, c0w, hcat);
        if (t < S_) {
            __nv_bfloat16* hh = (t > 0) ? (H1_h + (size_t)(t - 1) * B_ * H_) : nullptr;
            __nv_bfloat16* hl = (t > 0) ? (H1_l + (size_t)(t - 1) * B_ * H_) : nullptr;
            stepB_kernel<<<dim3(8, 8), 256>>>(Wh, part1, part0, b1eff, c1s, hcat, hh, hl);
        } else {
            cell_combine_kernel<<<16, 256>>>(part1, b1eff, c1s,
                                             H1_h + (size_t)(S_ - 1) * B_ * H_,
                                             H1_l + (size_t)(S_ - 1) * B_ * H_);
        }
    }

    // ---- output path ----
    // ys = H1s @ Wxh1 + bxh1  [4096,512]@[512,512] (bf16 3-term, fp32 out)
    bfp_gemm_kernel<<<dim3(S_ * B_ / 128, D_ / 128), 256, BFP_SMEM>>>(
        H1_h, H1_l, Wx1_h, Wx1_l, bxh + D_, ys, S_ * B_, D_, H_, 0);
    // ys -> exact fp16 pair
    split_h_kernel<<<(S_ * B_ * D_ / 8 + 255) / 256, 256>>>(ys, ysh_h, ysh_l,
                                                            S_ * B_ * D_ / 8);
    // logits = ys @ Wc + bc   [4096,512]@[512,32000]  (fp16 2-term), rows (t,b)->(b,t)
    hfp_gemm_kernel<<<dim3(S_ * B_ / 128, V_ / 128), 256, HFP_SMEM>>>(
        ysh_h, ysh_l, Wc16, bc, out, S_ * B_, V_, D_, 1);
}

// round 17
// speedup vs baseline: 1.8862x; 1.1721x over previous
#include <cuda_runtime.h>
#include <cuda_bf16.h>
#include <cuda_fp16.h>
#include <cstdint>

typedef unsigned long long ull;

#define B_  32
#define S_  128
#define H_  512
#define D_  512
#define V_  32000
#define F_  768
#define G4  2048   // 4*H

// ---------------- scratch (device globals; no allocation allowed) ----------------
__device__ float g_yim[B_ * D_];
__device__ float g_xU[(S_ + 1) * B_ * G4];
__device__ float g_Wcat[1024 * G4];              // [Wh1 ; M01=Wxh0@Uh1]
__device__ float g_b0eff[G4];
__device__ float g_b1eff[G4];
__device__ float g_hcat[B_ * 1024];              // per row: [h1 | h0']
__device__ float g_c0a[B_ * H_];
__device__ float g_c0b[B_ * H_];
__device__ float g_c1s[B_ * H_];
__device__ float g_part0[8 * B_ * G4];
__device__ float g_part1[16 * B_ * G4];
__device__ float g_ys[S_ * B_ * D_];

// bf16 hi/lo operand arrays (3-term path: xU, ys)
__device__ __nv_bfloat16 g_Uh_h[512 * 2048], g_Uh_l[512 * 2048];
__device__ __nv_bfloat16 g_Wx1_h[512 * 512], g_Wx1_l[512 * 512];
__device__ __nv_bfloat16 g_Xg_h[4224 * 512], g_Xg_l[4224 * 512];   // padded 33*128 rows
__device__ __nv_bfloat16 g_H1s_h[4096 * 512], g_H1s_l[4096 * 512];

// fp16 operands (2-term classifier path)
__device__ __half g_Wc16[512 * 32000];           // Wc hi-only fp16
__device__ __half g_ysh_h[4096 * 512], g_ysh_l[4096 * 512];  // ys exact fp16 pair

// ---------------- helpers ----------------
__device__ __forceinline__ ull pack2(float x, float y) {
    ull r; asm("mov.b64 %0, {%1, %2};" : "=l"(r) : "f"(x), "f"(y)); return r;
}
__device__ __forceinline__ void ffma2(ull& d, ull a, ull b) {
    asm("fma.rn.f32x2 %0, %1, %2, %0;" : "+l"(d) : "l"(a), "l"(b));
}
__device__ __forceinline__ float2 unpack2(ull v) {
    float2 r; asm("mov.b64 {%0, %1}, %2;" : "=f"(r.x), "=f"(r.y) : "l"(v)); return r;
}
__device__ __forceinline__ uint32_t smem_u32(const void* p) {
    return (uint32_t)__cvta_generic_to_shared(p);
}

#define CPA16(dst, src) asm volatile( \
    "cp.async.cg.shared.global [%0], [%1], 16;" :: "r"(dst), "l"(src))
#define CPA_COMMIT asm volatile("cp.async.commit_group;")
#define CPA_WAIT2  asm volatile("cp.async.wait_group 2;")

// bf16 split of float4
__device__ __forceinline__ void split4(float4 v, uint2& ph, uint2& pl) {
    float a[4] = {v.x, v.y, v.z, v.w};
    unsigned h[4], l[4];
    #pragma unroll
    for (int q = 0; q < 4; q++) {
        __nv_bfloat16 hh = __float2bfloat16_rn(a[q]);
        h[q] = (unsigned)__bfloat16_as_ushort(hh);
        l[q] = (unsigned)__bfloat16_as_ushort(
                   __float2bfloat16_rn(a[q] - __bfloat162float(hh)));
    }
    ph = make_uint2(h[0] | (h[1] << 16), h[2] | (h[3] << 16));
    pl = make_uint2(l[0] | (l[1] << 16), l[2] | (l[3] << 16));
}

// fp16 split of float4 (exact hi+lo pair)
__device__ __forceinline__ void split4h(float4 v, uint2& ph, uint2& pl) {
    float a[4] = {v.x, v.y, v.z, v.w};
    unsigned h[4], l[4];
    #pragma unroll
    for (int q = 0; q < 4; q++) {
        __half hh = __float2half_rn(a[q]);
        h[q] = (unsigned)__half_as_ushort(hh);
        l[q] = (unsigned)__half_as_ushort(
                   __float2half_rn(a[q] - __half2float(hh)));
    }
    ph = make_uint2(h[0] | (h[1] << 16), h[2] | (h[3] << 16));
    pl = make_uint2(l[0] | (l[1] << 16), l[2] | (l[3] << 16));
}

// ---------------- init ----------------
__global__ void init_state_kernel(const float* __restrict__ h0,
                                  const float* __restrict__ c0,
                                  float* __restrict__ hcat,
                                  float* __restrict__ c0a,
                                  float* __restrict__ c1s) {
    int idx = blockIdx.x * 256 + threadIdx.x;   // 32768
    int l = idx >> 14, b = (idx >> 9) & 31, j = idx & 511;
    float h = h0[idx], c = c0[idx];
    if (l == 0) { hcat[b * 1024 + 512 + j] = h; c0a[b * 512 + j] = c; }
    else        { hcat[b * 1024 + j] = h;       c1s[b * 512 + j] = c; }
}

// ---------------- gather + bf16 split fused ----------------
__global__ void gather_kernel(const float* __restrict__ yim,
                              const float* __restrict__ embed,
                              const int* __restrict__ tokens,
                              __nv_bfloat16* __restrict__ Xh,
                              __nv_bfloat16* __restrict__ Xl) {
    int v = blockIdx.x * 256 + threadIdx.x;     // float4 units
    int d4 = v & 127;
    int bt = v >> 7;
    int b = bt & 31;
    int t = bt >> 5;
    const float4* src;
    if (t == 0) src = (const float4*)(yim + b * 512);
    else        src = (const float4*)(embed + (size_t)tokens[b * 128 + (t - 1)] * 512);
    float4 x = src[d4];
    uint2 ph, pl;
    split4(x, ph, pl);
    size_t o = (size_t)bt * 512 + d4 * 4;
    *(uint2*)(Xh + o) = ph;
    *(uint2*)(Xl + o) = pl;
}

// ---------------- bias folds ----------------
__global__ void b1eff_kernel(const float* __restrict__ bw, const float* __restrict__ bu,
                             const float* __restrict__ bxh, const float* __restrict__ Uh,
                             float* __restrict__ b1, float* __restrict__ b0) {
    int n = blockIdx.x * 256 + threadIdx.x;     // 2048
    b0[n] = bw[n] + bu[n];
    float acc = bw[2048 + n] + bu[2048 + n];
    const float* U1 = Uh + 512 * 2048;
    for (int k = 0; k < 512; k++) acc += bxh[k] * U1[k * 2048 + n];
    b1[n] = acc;
}

// ---------------- fp32 -> bf16 hi/lo split ----------------
__global__ void split_kernel(const float* __restrict__ in,
                             __nv_bfloat16* __restrict__ hi,
                             __nv_bfloat16* __restrict__ lo, int n8) {
    int i = blockIdx.x * 256 + threadIdx.x;
    if (i >= n8) return;
    float4 a = ((const float4*)in)[2 * i];
    float4 b = ((const float4*)in)[2 * i + 1];
    uint2 ph0, pl0, ph1, pl1;
    split4(a, ph0, pl0);
    split4(b, ph1, pl1);
    ((uint4*)hi)[i] = make_uint4(ph0.x, ph0.y, ph1.x, ph1.y);
    ((uint4*)lo)[i] = make_uint4(pl0.x, pl0.y, pl1.x, pl1.y);
}

// ---------------- fp32 -> fp16 hi/lo pair split (for ys) ----------------
__global__ void split_h_kernel(const float* __restrict__ in,
                               __half* __restrict__ hi,
                               __half* __restrict__ lo, int n8) {
    int i = blockIdx.x * 256 + threadIdx.x;
    if (i >= n8) return;
    float4 a = ((const float4*)in)[2 * i];
    float4 b = ((const float4*)in)[2 * i + 1];
    uint2 ph0, pl0, ph1, pl1;
    split4h(a, ph0, pl0);
    split4h(b, ph1, pl1);
    ((uint4*)hi)[i] = make_uint4(ph0.x, ph0.y, ph1.x, ph1.y);
    ((uint4*)lo)[i] = make_uint4(pl0.x, pl0.y, pl1.x, pl1.y);
}

// ---------------- fp32 -> fp16 convert (Wc hi-only) ----------------
__global__ void convert_h_kernel(const float* __restrict__ in,
                                 __half* __restrict__ out, int n8) {
    int i = blockIdx.x * 256 + threadIdx.x;
    if (i >= n8) return;
    float4 a = ((const float4*)in)[2 * i];
    float4 b = ((const float4*)in)[2 * i + 1];
    float v[8] = {a.x, a.y, a.z, a.w, b.x, b.y, b.z, b.w};
    unsigned h[8];
    #pragma unroll
    for (int q = 0; q < 8; q++)
        h[q] = (unsigned)__half_as_ushort(__float2half_rn(v[q]));
    ((uint4*)out)[i] = make_uint4(h[0] | (h[1] << 16), h[2] | (h[3] << 16),
                                  h[4] | (h[5] << 16), h[6] | (h[7] << 16));
}

// ---------------- fp32 SGEMM (small setup matrices) ----------------
__global__ __launch_bounds__(256, 2) void sgemm_kernel(const float* __restrict__ A,
                                                       const float* __restrict__ Bm,
                                                       const float* __restrict__ bias,
                                                       float* __restrict__ C,
                                                       int M, int N, int K) {
    __shared__ __align__(16) float As[16][132];
    __shared__ __align__(16) float Bs[16][128];
    int tid = threadIdx.x;
    int m0 = blockIdx.y * 128, n0 = blockIdx.x * 128;
    int a_m = tid >> 2, a_k = (tid & 3) << 2;
    int b_k = tid >> 5, b_n = (tid & 31) << 2;
    int tm0 = (tid >> 4) << 3, tn0 = (tid & 15) << 3;
    ull acc[8][4];
    #pragma unroll
    for (int i = 0; i < 8; i++)
        #pragma unroll
        for (int j = 0; j < 4; j++) acc[i][j] = 0ULL;

    for (int k0 = 0; k0 < K; k0 += 16) {
        #pragma unroll
        for (int h = 0; h < 2; h++) {
            int gm = m0 + a_m + h * 64;
            float4 av = make_float4(0.f, 0.f, 0.f, 0.f);
            if (gm < M) av = *(const float4*)(A + (size_t)gm * K + k0 + a_k);
            As[a_k + 0][a_m + h * 64] = av.x;
            As[a_k + 1][a_m + h * 64] = av.y;
            As[a_k + 2][a_m + h * 64] = av.z;
            As[a_k + 3][a_m + h * 64] = av.w;
        }
        #pragma unroll
        for (int h = 0; h < 2; h++) {
            int gk = k0 + b_k + h * 8;
            *(float4*)&Bs[b_k + h * 8][b_n] = *(const float4*)(Bm + (size_t)gk * N + n0 + b_n);
        }
        __syncthreads();
        #pragma unroll
        for (int kk = 0; kk < 16; kk++) {
            float4 a0 = *(const float4*)&As[kk][tm0];
            float4 a1 = *(const float4*)&As[kk][tm0 + 4];
            ull b2[4];
            #pragma unroll
            for (int j = 0; j < 4; j++) b2[j] = *(const ull*)&Bs[kk][tn0 + 2 * j];
            float av[8] = {a0.x, a0.y, a0.z, a0.w, a1.x, a1.y, a1.z, a1.w};
            #pragma unroll
            for (int i = 0; i < 8; i++) {
                ull a2 = pack2(av[i], av[i]);
                #pragma unroll
                for (int j = 0; j < 4; j++) ffma2(acc[i][j], a2, b2[j]);
            }
        }
        __syncthreads();
    }
    #pragma unroll
    for (int i = 0; i < 8; i++) {
        int r = m0 + tm0 + i;
        if (r < M) {
            float o_[8];
            #pragma unroll
            for (int j = 0; j < 4; j++) {
                float2 v = unpack2(acc[i][j]);
                o_[2 * j] = v.x; o_[2 * j + 1] = v.y;
            }
            if (bias) {
                #pragma unroll
                for (int j = 0; j < 8; j++) o_[j] += bias[n0 + tn0 + j];
            }
            float* cp = C + (size_t)r * N + n0 + tn0;
            *(float4*)cp = make_float4(o_[0], o_[1], o_[2], o_[3]);
            *(float4*)(cp + 4) = make_float4(o_[4], o_[5], o_[6], o_[7]);
        }
    }
}

// ---------------- shared MMA macros ----------------
#define LDSM4(r, addr) asm volatile( \
    "ldmatrix.sync.aligned.m8n8.x4.shared.b16 {%0,%1,%2,%3}, [%4];" \
    : "=r"((r)[0]), "=r"((r)[1]), "=r"((r)[2]), "=r"((r)[3]) : "r"(addr))
#define LDSM4T(r, addr) asm volatile( \
    "ldmatrix.sync.aligned.m8n8.x4.trans.shared.b16 {%0,%1,%2,%3}, [%4];" \
    : "=r"((r)[0]), "=r"((r)[1]), "=r"((r)[2]), "=r"((r)[3]) : "r"(addr))
#define MMA16816(d, a, b) asm volatile( \
    "mma.sync.aligned.m16n8k16.row.col.f32.bf16.bf16.f32 " \
    "{%0,%1,%2,%3}, {%4,%5,%6,%7}, {%8,%9}, {%0,%1,%2,%3};" \
    : "+f"((d)[0]), "+f"((d)[1]), "+f"((d)[2]), "+f"((d)[3]) \
    : "r"((a)[0]), "r"((a)[1]), "r"((a)[2]), "r"((a)[3]), "r"((b)[0]), "r"((b)[1]))
#define MMAH16816(d, a, b) asm volatile( \
    "mma.sync.aligned.m16n8k16.row.col.f32.f16.f16.f32 " \
    "{%0,%1,%2,%3}, {%4,%5,%6,%7}, {%8,%9}, {%0,%1,%2,%3};" \
    : "+f"((d)[0]), "+f"((d)[1]), "+f"((d)[2]), "+f"((d)[3]) \
    : "r"((a)[0]), "r"((a)[1]), "r"((a)[2]), "r"((a)[3]), "r"((b)[0]), "r"((b)[1]))

// ---------------- bf16 3-term GEMM, 3-stage cp.async pipeline (xU, ys) ----------------
#define BFP_A_ST 6144
#define BFP_B_ST 4352
#define BFP_OAL 18432
#define BFP_OBH 36864
#define BFP_OBL 49920
#define BFP_SMEM 62976

__global__ __launch_bounds__(256) void bfp_gemm_kernel(
    const __nv_bfloat16* __restrict__ Ah, const __nv_bfloat16* __restrict__ Al,
    const __nv_bfloat16* __restrict__ Bh, const __nv_bfloat16* __restrict__ Bl,
    const float* __restrict__ bias, float* __restrict__ C,
    int M, int N, int K, int permute) {
    extern __shared__ __align__(16) char smdyn[];
    uint32_t sb = smem_u32(smdyn);
    int tid = threadIdx.x;
    int lane = tid & 31, wid = tid >> 5;
    int wm = wid >> 2, wn = wid & 3;
    int m0 = blockIdx.x * 128, n0 = blockIdx.y * 128;

    uint32_t aAh[4], aAl[4], aBh[2], aBl[2];
    {
        int r = lane & 15, c2 = (lane >> 4) * 8;
        #pragma unroll
        for (int i = 0; i < 4; i++) {
            int row = wm * 64 + i * 16 + r;
            aAh[i] = sb + row * 48 + c2 * 2;
            aAl[i] = sb + BFP_OAL + row * 48 + c2 * 2;
        }
        #pragma unroll
        for (int j2 = 0; j2 < 2; j2++) {
            int col = wn * 32 + j2 * 16 + c2;
            aBh[j2] = sb + BFP_OBH + r * 272 + col * 2;
            aBl[j2] = sb + BFP_OBL + r * 272 + col * 2;
        }
    }

    float acc[4][4][4];
    #pragma unroll
    for (int i = 0; i < 4; i++)
        #pragma unroll
        for (int j = 0; j < 4; j++)
            #pragma unroll
            for (int q = 0; q < 4; q++) acc[i][j][q] = 0.f;

    int arow = tid >> 1, ac0 = (tid & 1) * 8;
    int brow = tid >> 4, bc0 = (tid & 15) * 8;
    const __nv_bfloat16* gAh = Ah + (size_t)(m0 + arow) * K + ac0;
    const __nv_bfloat16* gAl = Al + (size_t)(m0 + arow) * K + ac0;
    const __nv_bfloat16* gBh = Bh + (size_t)brow * N + n0 + bc0;
    const __nv_bfloat16* gBl = Bl + (size_t)brow * N + n0 + bc0;
    uint32_t dAh = sb + arow * 48 + ac0 * 2;
    uint32_t dAl = sb + BFP_OAL + arow * 48 + ac0 * 2;
    uint32_t dBh = sb + BFP_OBH + brow * 272 + bc0 * 2;
    uint32_t dBl = sb + BFP_OBL + brow * 272 + bc0 * 2;

#define BFP_FILL(st, kc) do { \
        CPA16(dAh + (st) * BFP_A_ST, gAh + (kc) * 16); \
        CPA16(dAl + (st) * BFP_A_ST, gAl + (kc) * 16); \
        CPA16(dBh + (st) * BFP_B_ST, gBh + (size_t)(kc) * 16 * N); \
        CPA16(dBl + (st) * BFP_B_ST, gBl + (size_t)(kc) * 16 * N); \
        CPA_COMMIT; \
    } while (0)

    int nk = K / 16;
    BFP_FILL(0, 0);
    BFP_FILL(1, 1);

    int s = 0, fs = 2;
    for (int k = 0; k < nk; k++) {
        if (k + 2 < nk) { BFP_FILL(fs, k + 2); fs = (fs == 2) ? 0 : fs + 1; }
        else            { CPA_COMMIT; }
        CPA_WAIT2;
        __syncthreads();
        uint32_t sA = s * BFP_A_ST, sB2 = s * BFP_B_ST;
        uint32_t af[4][4], bh[4][2], bl[4][2];
        #pragma unroll
        for (int i = 0; i < 4; i++) LDSM4(af[i], aAh[i] + sA);
        #pragma unroll
        for (int j2 = 0; j2 < 2; j2++) {
            uint32_t t4[4];
            LDSM4T(t4, aBh[j2] + sB2);
            bh[2 * j2][0] = t4[0]; bh[2 * j2][1] = t4[1];
            bh[2 * j2 + 1][0] = t4[2]; bh[2 * j2 + 1][1] = t4[3];
        }
        #pragma unroll
        for (int i = 0; i < 4; i++)
            #pragma unroll
            for (int j = 0; j < 4; j++) MMA16816(acc[i][j], af[i], bh[j]);
        #pragma unroll
        for (int j2 = 0; j2 < 2; j2++) {
            uint32_t t4[4];
            LDSM4T(t4, aBl[j2] + sB2);
            bl[2 * j2][0] = t4[0]; bl[2 * j2][1] = t4[1];
            bl[2 * j2 + 1][0] = t4[2]; bl[2 * j2 + 1][1] = t4[3];
        }
        #pragma unroll
        for (int i = 0; i < 4; i++)
            #pragma unroll
            for (int j = 0; j < 4; j++) MMA16816(acc[i][j], af[i], bl[j]);
        #pragma unroll
        for (int i = 0; i < 4; i++) LDSM4(af[i], aAl[i] + sA);
        #pragma unroll
        for (int i = 0; i < 4; i++)
            #pragma unroll
            for (int j = 0; j < 4; j++) MMA16816(acc[i][j], af[i], bh[j]);
        __syncthreads();
        s = (s == 2) ? 0 : s + 1;
    }

    #pragma unroll
    for (int i = 0; i < 4; i++) {
        int r0 = m0 + wm * 64 + i * 16 + (lane >> 2);
        #pragma unroll
        for (int h = 0; h < 2; h++) {
            int r = r0 + h * 8;
            if (r < M) {
                int ro = permute ? ((r & 31) * 128 + (r >> 5)) : r;
                #pragma unroll
                for (int j = 0; j < 4; j++) {
                    int c = n0 + wn * 32 + j * 8 + (lane & 3) * 2;
                    float x0 = acc[i][j][h * 2], x1 = acc[i][j][h * 2 + 1];
                    if (bias) { x0 += bias[c]; x1 += bias[c + 1]; }
                    *(float2*)(C + (size_t)ro * N + c) = make_float2(x0, x1);
                }
            }
        }
    }
}

// ---------------- fp16 2-term GEMM (classifier): C = (Ah+Al)@Bh + bias ----------------
#define HFP_A_ST 6144
#define HFP_B_ST 4352
#define HFP_OAL 18432
#define HFP_OBH 36864
#define HFP_SMEM 49920

__global__ __launch_bounds__(256) void hfp_gemm_kernel(
    const __half* __restrict__ Ah, const __half* __restrict__ Al,
    const __half* __restrict__ Bh,
    const float* __restrict__ bias, float* __restrict__ C,
    int M, int N, int K, int permute) {
    extern __shared__ __align__(16) char smdyn[];
    uint32_t sb = smem_u32(smdyn);
    int tid = threadIdx.x;
    int lane = tid & 31, wid = tid >> 5;
    int wm = wid >> 2, wn = wid & 3;             // 2 x 4 warps, warp tile 64m x 32n
    int m0 = blockIdx.x * 128, n0 = blockIdx.y * 128;

    uint32_t aAh[4], aAl[4], aBh[2];
    {
        int r = lane & 15, c2 = (lane >> 4) * 8;
        #pragma unroll
        for (int i = 0; i < 4; i++) {
            int row = wm * 64 + i * 16 + r;
            aAh[i] = sb + row * 48 + c2 * 2;
            aAl[i] = sb + HFP_OAL + row * 48 + c2 * 2;
        }
        #pragma unroll
        for (int j2 = 0; j2 < 2; j2++) {
            int col = wn * 32 + j2 * 16 + c2;
            aBh[j2] = sb + HFP_OBH + r * 272 + col * 2;
        }
    }

    float acc[4][4][4];
    #pragma unroll
    for (int i = 0; i < 4; i++)
        #pragma unroll
        for (int j = 0; j < 4; j++)
            #pragma unroll
            for (int q = 0; q < 4; q++) acc[i][j][q] = 0.f;

    int arow = tid >> 1, ac0 = (tid & 1) * 8;
    int brow = tid >> 4, bc0 = (tid & 15) * 8;
    const __half* gAh = Ah + (size_t)(m0 + arow) * K + ac0;
    const __half* gAl = Al + (size_t)(m0 + arow) * K + ac0;
    const __half* gBh = Bh + (size_t)brow * N + n0 + bc0;
    uint32_t dAh = sb + arow * 48 + ac0 * 2;
    uint32_t dAl = sb + HFP_OAL + arow * 48 + ac0 * 2;
    uint32_t dBh = sb + HFP_OBH + brow * 272 + bc0 * 2;

#define HFP_FILL(st, kc) do { \
        CPA16(dAh + (st) * HFP_A_ST, gAh + (kc) * 16); \
        CPA16(dAl + (st) * HFP_A_ST, gAl + (kc) * 16); \
        CPA16(dBh + (st) * HFP_B_ST, gBh + (size_t)(kc) * 16 * N); \
        CPA_COMMIT; \
    } while (0)

    int nk = K / 16;
    HFP_FILL(0, 0);
    HFP_FILL(1, 1);

    int s = 0, fs = 2;
    for (int k = 0; k < nk; k++) {
        if (k + 2 < nk) { HFP_FILL(fs, k + 2); fs = (fs == 2) ? 0 : fs + 1; }
        else            { CPA_COMMIT; }
        CPA_WAIT2;
        __syncthreads();
        uint32_t sA = s * HFP_A_ST, sB2 = s * HFP_B_ST;
        uint32_t af[4][4], bh[4][2];
        #pragma unroll
        for (int j2 = 0; j2 < 2; j2++) {
            uint32_t t4[4];
            LDSM4T(t4, aBh[j2] + sB2);
            bh[2 * j2][0] = t4[0]; bh[2 * j2][1] = t4[1];
            bh[2 * j2 + 1][0] = t4[2]; bh[2 * j2 + 1][1] = t4[3];
        }
        #pragma unroll
        for (int i = 0; i < 4; i++) LDSM4(af[i], aAh[i] + sA);
        #pragma unroll
        for (int i = 0; i < 4; i++)
            #pragma unroll
            for (int j = 0; j < 4; j++) MMAH16816(acc[i][j], af[i], bh[j]);  // hi@B
        #pragma unroll
        for (int i = 0; i < 4; i++) LDSM4(af[i], aAl[i] + sA);
        #pragma unroll
        for (int i = 0; i < 4; i++)
            #pragma unroll
            for (int j = 0; j < 4; j++) MMAH16816(acc[i][j], af[i], bh[j]);  // lo@B
        __syncthreads();
        s = (s == 2) ? 0 : s + 1;
    }

    #pragma unroll
    for (int i = 0; i < 4; i++) {
        int r0 = m0 + wm * 64 + i * 16 + (lane >> 2);
        #pragma unroll
        for (int h = 0; h < 2; h++) {
            int r = r0 + h * 8;
            if (r < M) {
                int ro = permute ? ((r & 31) * 128 + (r >> 5)) : r;
                #pragma unroll
                for (int j = 0; j < 4; j++) {
                    int c = n0 + wn * 32 + j * 8 + (lane & 3) * 2;
                    float x0 = acc[i][j][h * 2], x1 = acc[i][j][h * 2 + 1];
                    if (bias) { x0 += bias[c]; x1 += bias[c + 1]; }
                    *(float2*)(C + (size_t)ro * N + c) = make_float2(x0, x1);
                }
            }
        }
    }
}

// ---------------- LSTM cell pieces ----------------
template<int NSL>
__device__ __forceinline__ void gates4(const float* __restrict__ part,
                                       const float* __restrict__ xU_t,
                                       const float* __restrict__ beff,
                                       int b, int j,
                                       float4& gf, float4& gi, float4& go, float4& gc) {
    gf = make_float4(0.f, 0.f, 0.f, 0.f); gi = gf; go = gf; gc = gf;
    const float* p = part + b * 2048 + j;
    #pragma unroll
    for (int s = 0; s < NSL; s++) {
        float4 a = *(const float4*)(p);
        float4 bq = *(const float4*)(p + 512);
        float4 cq = *(const float4*)(p + 1024);
        float4 dq = *(const float4*)(p + 1536);
        gf.x += a.x;  gf.y += a.y;  gf.z += a.z;  gf.w += a.w;
        gi.x += bq.x; gi.y += bq.y; gi.z += bq.z; gi.w += bq.w;
        go.x += cq.x; go.y += cq.y; go.z += cq.z; go.w += cq.w;
        gc.x += dq.x; gc.y += dq.y; gc.z += dq.z; gc.w += dq.w;
        p += 32 * 2048;
    }
    if (xU_t) {
        const float* x = xU_t + b * 2048 + j;
        float4 a = *(const float4*)(x);
        float4 bq = *(const float4*)(x + 512);
        float4 cq = *(const float4*)(x + 1024);
        float4 dq = *(const float4*)(x + 1536);
        gf.x += a.x;  gf.y += a.y;  gf.z += a.z;  gf.w += a.w;
        gi.x += bq.x; gi.y += bq.y; gi.z += bq.z; gi.w += bq.w;
        go.x += cq.x; go.y += cq.y; go.z += cq.z; go.w += cq.w;
        gc.x += dq.x; gc.y += dq.y; gc.z += dq.z; gc.w += dq.w;
    }
    float4 a = *(const float4*)(beff + j);
    float4 bq = *(const float4*)(beff + 512 + j);
    float4 cq = *(const float4*)(beff + 1024 + j);
    float4 dq = *(const float4*)(beff + 1536 + j);
    gf.x += a.x;  gf.y += a.y;  gf.z += a.z;  gf.w += a.w;
    gi.x += bq.x; gi.y += bq.y; gi.z += bq.z; gi.w += bq.w;
    go.x += cq.x; go.y += cq.y; go.z += cq.z; go.w += cq.w;
    gc.x += dq.x; gc.y += dq.y; gc.z += dq.z; gc.w += dq.w;
}

__device__ __forceinline__ float2 lstm_update(float gf, float gi, float go, float gc,
                                              float c_old) {
    float f  = 1.f / (1.f + __expf(-gf));
    float ii = 1.f / (1.f + __expf(-gi));
    float o  = 1.f / (1.f + __expf(-go));
    float cn = f * c_old + ii * tanhf(gc);
    float hn = o * tanhf(cn);
    return make_float2(hn, cn);
}

__device__ __forceinline__ void lstm4(float4 gf, float4 gi, float4 go, float4 gc,
                                      float4 co, float4& hn, float4& cn) {
    float2 r0 = lstm_update(gf.x, gi.x, go.x, gc.x, co.x);
    float2 r1 = lstm_update(gf.y, gi.y, go.y, gc.y, co.y);
    float2 r2 = lstm_update(gf.z, gi.z, go.z, gc.z, co.z);
    float2 r3 = lstm_update(gf.w, gi.w, go.w, gc.w, co.w);
    hn = make_float4(r0.x, r1.x, r2.x, r3.x);
    cn = make_float4(r0.y, r1.y, r2.y, r3.y);
}

__device__ __forceinline__ void gemm64(const float* __restrict__ Wp,
                                       float* __restrict__ pout,
                                       float (*hs)[36]) {
    ull acc[16];
    #pragma unroll
    for (int q = 0; q < 16; q++) acc[q] = 0ULL;
    for (int k0 = 0; k0 < 64; k0 += 8) {
        float wv[8];
        #pragma unroll
        for (int j = 0; j < 8; j++) wv[j] = Wp[(size_t)(k0 + j) * 2048];
        #pragma unroll
        for (int j = 0; j < 8; j++) {
            ull w2 = pack2(wv[j], wv[j]);
            const float* hr = &hs[k0 + j][0];
            #pragma unroll
            for (int p = 0; p < 8; p++) {
                ulonglong2 hh = *(const ulonglong2*)(hr + p * 4);
                ffma2(acc[2 * p], w2, hh.x);
                ffma2(acc[2 * p + 1], w2, hh.y);
            }
        }
    }
    #pragma unroll
    for (int q = 0; q < 16; q++) {
        float2 v = unpack2(acc[q]);
        pout[(2 * q) * 2048] = v.x;
        pout[(2 * q + 1) * 2048] = v.y;
    }
}

// bootstrap layer-0 GEMM (t=0): grid (16,8), 128 thr
__global__ __launch_bounds__(128) void cell_gemm_kernel(const float* __restrict__ A,
                                                        const float* __restrict__ W,
                                                        float* __restrict__ part) {
    __shared__ __align__(16) float hs[64][36];
    int tid = threadIdx.x;
    int kbase = blockIdx.y * 64;
    for (int i = tid; i < 2048; i += 128) {
        int b = i >> 6, kk = i & 63;
        hs[kk][b] = A[b * 1024 + kbase + kk];
    }
    __syncthreads();
    int ncol = blockIdx.x * 128 + tid;
    gemm64(W + (size_t)kbase * 2048 + ncol,
           part + (size_t)(blockIdx.y * 32) * 2048 + ncol, hs);
}

// combine0: standalone, fully coalesced.  grid 16 CTAs x 256 thr.
__global__ void combine0_kernel(const float* __restrict__ part0,
                                const float* __restrict__ xU_t,
                                const float* __restrict__ b0eff,
                                const float* __restrict__ c0_old,
                                float* __restrict__ c0_new,
                                float* __restrict__ hcat) {
    int idx = (blockIdx.x * 256 + threadIdx.x) * 4;   // 16384 values
    int b = idx >> 9, j = idx & 511;
    float4 gf, gi, go, gc, hn, cn;
    gates4<8>(part0, xU_t, b0eff, b, j, gf, gi, go, gc);
    lstm4(gf, gi, go, gc, *(const float4*)(c0_old + idx), hn, cn);
    *(float4*)(c0_new + idx) = cn;
    *(float4*)(hcat + b * 1024 + 512 + j) = hn;       // h0'
}

// step A: pure layer-1 GEMM from hcat.  grid (8 nb, 16 ks), 256 threads.
__global__ __launch_bounds__(256) void stepA_kernel(
    const float* __restrict__ Wcat, float* __restrict__ part1,
    const float* __restrict__ hcat) {
    __shared__ __align__(16) float hs[64][36];
    int tid = threadIdx.x, nb = blockIdx.x, ks = blockIdx.y;
    for (int c = tid; c < 512; c += 256) {
        int bb = c >> 4, k4 = (c & 15) * 4;
        float4 v = *(const float4*)(hcat + bb * 1024 + ks * 64 + k4);
        hs[k4 + 0][bb] = v.x; hs[k4 + 1][bb] = v.y;
        hs[k4 + 2][bb] = v.z; hs[k4 + 3][bb] = v.w;
    }
    __syncthreads();
    int ncol = nb * 256 + tid;
    gemm64(Wcat + (size_t)(ks * 64) * 2048 + ncol,
           part1 + (size_t)(ks * 32) * 2048 + ncol, hs);
}

// step B: fused combine1 + next step's layer-0 GEMM.  grid (8 nb, 8 ks), 256 threads.
__global__ __launch_bounds__(256) void stepB_kernel(
    const float* __restrict__ Wh, const float* __restrict__ part1,
    float* __restrict__ part0, const float* __restrict__ b1eff,
    float* __restrict__ c1s, float* __restrict__ hcat,
    __nv_bfloat16* __restrict__ H1h_t, __nv_bfloat16* __restrict__ H1l_t) {
    __shared__ __align__(16) float hs[64][36];
    int tid = threadIdx.x, nb = blockIdx.x, ks = blockIdx.y;
    {
        int g = (ks * 8 + nb) * 256 + tid;
        if (g < 4096) {
            int idx = g * 4;
            int b = idx >> 9, j = idx & 511;
            float4 gf, gi, go, gc, hn, cn;
            gates4<16>(part1, nullptr, b1eff, b, j, gf, gi, go, gc);
            lstm4(gf, gi, go, gc, *(const float4*)(c1s + idx), hn, cn);
            *(float4*)(c1s + idx) = cn;
            *(float4*)(hcat + b * 1024 + j) = hn;
            if (H1h_t) {
                uint2 ph, pl;
                split4(hn, ph, pl);
                *(uint2*)(H1h_t + idx) = ph;
                *(uint2*)(H1l_t + idx) = pl;
            }
        }
    }
    // layer-0 GEMM reads only h0' (written by combine0) — independent of combine1
    for (int c = tid; c < 512; c += 256) {
        int bb = c >> 4, k4 = (c & 15) * 4;
        float4 v = *(const float4*)(hcat + bb * 1024 + 512 + ks * 64 + k4);
        hs[k4 + 0][bb] = v.x; hs[k4 + 1][bb] = v.y;
        hs[k4 + 2][bb] = v.z; hs[k4 + 3][bb] = v.w;
    }
    __syncthreads();
    int ncol = nb * 256 + tid;
    gemm64(Wh + (size_t)(ks * 64) * 2048 + ncol,
           part0 + (size_t)(ks * 32) * 2048 + ncol, hs);
}

// final standalone combine (t = S)
__global__ void cell_combine_kernel(const float* __restrict__ part,
                                    const float* __restrict__ b1eff,
                                    float* __restrict__ c1s,
                                    __nv_bfloat16* __restrict__ h1h,
                                    __nv_bfloat16* __restrict__ h1l) {
    int idx = (blockIdx.x * 256 + threadIdx.x) * 4;
    int b = idx >> 9, j = idx & 511;
    float4 gf, gi, go, gc, hn, cn;
    gates4<16>(part, nullptr, b1eff, b, j, gf, gi, go, gc);
    lstm4(gf, gi, go, gc, *(const float4*)(c1s + idx), hn, cn);
    *(float4*)(c1s + idx) = cn;
    uint2 ph, pl;
    split4(hn, ph, pl);
    *(uint2*)(h1h + idx) = ph;
    *(uint2*)(h1l + idx) = pl;
}

// ---------------- host orchestration ----------------
extern "C" void kernel_launch(void* const* d_in, const int* in_sizes, int n_in,
                              void* d_out, int out_size) {
    const float* im_feat = (const float*)d_in[0];
    const int*   tokens  = (const int*)d_in[1];
    const float* h0      = (const float*)d_in[2];
    const float* c0      = (const float*)d_in[3];
    const float* embed   = (const float*)d_in[4];
    const float* W_im    = (const float*)d_in[5];
    const float* b_im    = (const float*)d_in[6];
    const float* Wh      = (const float*)d_in[7];
    const float* bw      = (const float*)d_in[8];
    const float* Uh      = (const float*)d_in[9];
    const float* bu      = (const float*)d_in[10];
    const float* Wxh     = (const float*)d_in[11];
    const float* bxh     = (const float*)d_in[12];
    const float* Wc      = (const float*)d_in[13];
    const float* bc      = (const float*)d_in[14];
    float* out = (float*)d_out;

    float *yim, *xU, *Wcat, *b0eff, *b1eff, *hcat, *c0a, *c0b, *c1s,
          *part0, *part1, *ys;
    __nv_bfloat16 *Uh_h, *Uh_l, *Wx1_h, *Wx1_l, *Xg_h, *Xg_l, *H1_h, *H1_l;
    __half *Wc16, *ysh_h, *ysh_l;
    cudaGetSymbolAddress((void**)&yim,   g_yim);
    cudaGetSymbolAddress((void**)&xU,    g_xU);
    cudaGetSymbolAddress((void**)&Wcat,  g_Wcat);
    cudaGetSymbolAddress((void**)&b0eff, g_b0eff);
    cudaGetSymbolAddress((void**)&b1eff, g_b1eff);
    cudaGetSymbolAddress((void**)&hcat,  g_hcat);
    cudaGetSymbolAddress((void**)&c0a,   g_c0a);
    cudaGetSymbolAddress((void**)&c0b,   g_c0b);
    cudaGetSymbolAddress((void**)&c1s,   g_c1s);
    cudaGetSymbolAddress((void**)&part0, g_part0);
    cudaGetSymbolAddress((void**)&part1, g_part1);
    cudaGetSymbolAddress((void**)&ys,    g_ys);
    cudaGetSymbolAddress((void**)&Uh_h,  g_Uh_h);
    cudaGetSymbolAddress((void**)&Uh_l,  g_Uh_l);
    cudaGetSymbolAddress((void**)&Wx1_h, g_Wx1_h);
    cudaGetSymbolAddress((void**)&Wx1_l, g_Wx1_l);
    cudaGetSymbolAddress((void**)&Xg_h,  g_Xg_h);
    cudaGetSymbolAddress((void**)&Xg_l,  g_Xg_l);
    cudaGetSymbolAddress((void**)&H1_h,  g_H1s_h);
    cudaGetSymbolAddress((void**)&H1_l,  g_H1s_l);
    cudaGetSymbolAddress((void**)&Wc16,  g_Wc16);
    cudaGetSymbolAddress((void**)&ysh_h, g_ysh_h);
    cudaGetSymbolAddress((void**)&ysh_l, g_ysh_l);

    cudaFuncSetAttribute(bfp_gemm_kernel,
                         cudaFuncAttributeMaxDynamicSharedMemorySize, BFP_SMEM);
    cudaFuncSetAttribute(hfp_gemm_kernel,
                         cudaFuncAttributeMaxDynamicSharedMemorySize, HFP_SMEM);

    // ---- setup ----
    init_state_kernel<<<128, 256>>>(h0, c0, hcat, c0a, c1s);
    sgemm_kernel<<<dim3(D_ / 128, 1), 256>>>(im_feat, W_im, b_im, yim, B_, D_, F_);
    gather_kernel<<<((S_ + 1) * B_ * D_ / 4) / 256, 256>>>(yim, embed, tokens,
                                                           Xg_h, Xg_l);

    // weight splits / converts (independent)
    split_kernel<<<(512 * 2048 / 8 + 255) / 256, 256>>>(Uh, Uh_h, Uh_l, 512 * 2048 / 8);
    split_kernel<<<(512 * 512 / 8 + 255) / 256, 256>>>(Wxh + (size_t)H_ * D_,
                                                       Wx1_h, Wx1_l, 512 * 512 / 8);
    convert_h_kernel<<<(512 * 32000 / 8 + 255) / 256, 256>>>(Wc, Wc16, 512 * 32000 / 8);

    // xU = Xg @ Uh0   [4128,512]@[512,2048]  (bf16 3-term)
    bfp_gemm_kernel<<<dim3(33, G4 / 128), 256, BFP_SMEM>>>(
        Xg_h, Xg_l, Uh_h, Uh_l, nullptr, xU, (S_ + 1) * B_, G4, D_, 0);
    // Wcat = [Wh1 ; Wxh0 @ Uh1]  (fp32)
    cudaMemcpyAsync(Wcat, Wh + (size_t)H_ * G4, sizeof(float) * H_ * G4,
                    cudaMemcpyDeviceToDevice, 0);
    sgemm_kernel<<<dim3(G4 / 128, H_ / 128), 256>>>(
        Wxh, Uh + (size_t)D_ * G4, nullptr, Wcat + (size_t)H_ * G4, H_, G4, H_);
    b1eff_kernel<<<G4 / 256, 256>>>(bw, bu, bxh, Uh, b1eff, b0eff);

    // ---- recurrence: bootstrap + 3 kernels per step (all coalesced) ----
    cell_gemm_kernel<<<dim3(16, 8), 128>>>(hcat + 512, Wh, part0);
    for (int t = 0; t <= S_; t++) {
        const float* c0r = (t & 1) ? c0b : c0a;
        float* c0w       = (t & 1) ? c0a : c0b;
        combine0_kernel<<<16, 256>>>(part0, xU + (size_t)t * B_ * G4,
                                     b0eff, c0r, c0w, hcat);
        stepA_kernel<<<dim3(8, 16), 256>>>(Wcat, part1, hcat);
        if (t < S_) {
            __nv_bfloat16* hh = (t > 0) ? (H1_h + (size_t)(t - 1) * B_ * H_) : nullptr;
            __nv_bfloat16* hl = (t > 0) ? (H1_l + (size_t)(t - 1) * B_ * H_) : nullptr;
            stepB_kernel<<<dim3(8, 8), 256>>>(Wh, part1, part0, b1eff, c1s, hcat, hh, hl);
        } else {
            cell_combine_kernel<<<16, 256>>>(part1, b1eff, c1s,
                                             H1_h + (size_t)(S_ - 1) * B_ * H_,
                                             H1_l + (size_t)(S_ - 1) * B_ * H_);
        }
    }

    // ---- output path ----
    // ys = H1s @ Wxh1 + bxh1  [4096,512]@[512,512] (bf16 3-term, fp32 out)
    bfp_gemm_kernel<<<dim3(S_ * B_ / 128, D_ / 128), 256, BFP_SMEM>>>(
        H1_h, H1_l, Wx1_h, Wx1_l, bxh + D_, ys, S_ * B_, D_, H_, 0);
    // ys -> exact fp16 pair
    split_h_kernel<<<(S_ * B_ * D_ / 8 + 255) / 256, 256>>>(ys, ysh_h, ysh_l,
                                                            S_ * B_ * D_ / 8);
    // logits = ys @ Wc + bc   [4096,512]@[512,32000]  (fp16 2-term), rows (t,b)->(b,t)
    hfp_gemm_kernel<<<dim3(S_ * B_ / 128, V_ / 128), 256, HFP_SMEM>>>(
        ysh_h, ysh_l, Wc16, bc, out, S_ * B_, V_, D_, 1);
}